// round 2
// baseline (speedup 1.0000x reference)
#include <cuda_runtime.h>
#include <math.h>

// ---------------- problem constants ----------------
#define B_     16
#define N_     196
#define E_     512
#define H_     8
#define HD_    64
#define C_     2048
#define HDC_   256
#define FN_    784            // 4*N
#define BN_    3136           // B*N
#define NE_    100352         // N*E
#define FNE_   401408         // 4N*E
#define BNE_   1605632        // B*N*E
#define SCHZ_  38416          // 196*196
#define ATTZ_  153664         // 196*784

// ---------------- scratch (static device memory; no allocation) ----------------
__device__ float g_cx  [4*BN_*E_];       // [4,B,N,E] per-branch LN
__device__ float g_ec  [BN_*C_];         // [B,N,C]   concat LN
__device__ float g_qc  [BN_*C_];
__device__ float g_kc  [BN_*C_];
__device__ float g_vc  [BN_*C_];
__device__ float g_sch [B_*H_*N_*N_];    // channel scores
__device__ float g_t   [BN_*C_];         // s@v  (as [B,N,C])
__device__ float g_that[BN_*C_];         // T_hat
__device__ float g_kvs [B_*FN_*E_];      // KV_S
__device__ float g_Q   [4*BN_*E_];
__device__ float g_K   [B_*FN_*E_];
__device__ float g_V   [B_*FN_*E_];
__device__ float g_attn[512u*196*784];   // [g,b,h,N,4N]  315 MB
__device__ float g_mean[512];
__device__ float g_rstd[512];
__device__ float g_ctx [4*B_*H_*N_*HD_]; // [g,b,h,n,d]
__device__ float g_cm0 [BN_*E_];         // branch-0 permuted ctx
__device__ float g_h   [4*BN_*E_];       // residual-1 output
__device__ float g_xln [4*BN_*E_];
__device__ float g_x1  [4*BN_*2048];     // fc1 output
__device__ float g_qwT [4*N_*N_];
__device__ float g_kwT [FN_*FN_];
__device__ float g_vwT [FN_*FN_];

// ---------------- reductions ----------------
__device__ __forceinline__ float block_sum(float v, float* sh) {
    int tid = threadIdx.x;
    #pragma unroll
    for (int o = 16; o > 0; o >>= 1) v += __shfl_down_sync(0xffffffffu, v, o);
    if ((tid & 31) == 0) sh[tid >> 5] = v;
    __syncthreads();
    if (tid < 32) {
        float t = (tid < (int)(blockDim.x >> 5)) ? sh[tid] : 0.f;
        #pragma unroll
        for (int o = 16; o > 0; o >>= 1) t += __shfl_down_sync(0xffffffffu, t, o);
        if (tid == 0) sh[0] = t;
    }
    __syncthreads();
    float r = sh[0];
    __syncthreads();
    return r;
}

__device__ __forceinline__ float block_max(float v, float* sh) {
    int tid = threadIdx.x;
    #pragma unroll
    for (int o = 16; o > 0; o >>= 1) v = fmaxf(v, __shfl_down_sync(0xffffffffu, v, o));
    if ((tid & 31) == 0) sh[tid >> 5] = v;
    __syncthreads();
    if (tid < 32) {
        float t = (tid < (int)(blockDim.x >> 5)) ? sh[tid] : -INFINITY;
        #pragma unroll
        for (int o = 16; o > 0; o >>= 1) t = fmaxf(t, __shfl_down_sync(0xffffffffu, t, o));
        if (tid == 0) sh[0] = t;
    }
    __syncthreads();
    float r = sh[0];
    __syncthreads();
    return r;
}

// ---------------- fused LN: per-branch cx + concat ec ----------------
__global__ void __launch_bounds__(256) ln_fused_kernel(
    const float* __restrict__ e1, const float* __restrict__ e2,
    const float* __restrict__ e3, const float* __restrict__ e4,
    const float* __restrict__ lag, const float* __restrict__ lab,
    const float* __restrict__ lcg, const float* __restrict__ lcb,
    float* __restrict__ cx, float* __restrict__ ec)
{
    __shared__ float sh[32];
    int token = blockIdx.x;
    int tid = threadIdx.x;
    const float* es[4] = {e1, e2, e3, e4};
    float x[4][2], mg[4], rg[4];
    float stot = 0.f, sstot = 0.f;
    #pragma unroll
    for (int g = 0; g < 4; g++) {
        const float* p = es[g] + (long long)token * E_;
        x[g][0] = p[tid]; x[g][1] = p[tid + 256];
        float s  = block_sum(x[g][0] + x[g][1], sh);
        float ss = block_sum(x[g][0]*x[g][0] + x[g][1]*x[g][1], sh);
        float m = s * (1.f/512.f);
        float v = ss * (1.f/512.f) - m*m;
        mg[g] = m; rg[g] = rsqrtf(v + 1e-6f);
        stot += s; sstot += ss;
    }
    float m = stot * (1.f/2048.f);
    float r = rsqrtf(sstot * (1.f/2048.f) - m*m + 1e-6f);
    #pragma unroll
    for (int g = 0; g < 4; g++) {
        #pragma unroll
        for (int j = 0; j < 2; j++) {
            int e = tid + j*256;
            float xv = x[g][j];
            cx[((long long)g*BN_ + token)*E_ + e] =
                (xv - mg[g]) * rg[g] * lag[g*E_+e] + lab[g*E_+e];
            ec[(long long)token*C_ + g*E_ + e] =
                (xv - m) * r * lcg[g*E_+e] + lcb[g*E_+e];
        }
    }
}

// ---------------- rowwise LN (FFN) ----------------
__global__ void __launch_bounds__(256) ln_rows_kernel(
    const float* __restrict__ X, const float* __restrict__ gamma,
    const float* __restrict__ beta, float* __restrict__ Y, int rowsPerG)
{
    __shared__ float sh[32];
    long long row = blockIdx.x;
    int tid = threadIdx.x;
    int g = (int)(row / rowsPerG);
    const float* p = X + row * E_;
    float x0 = p[tid], x1 = p[tid+256];
    float s  = block_sum(x0 + x1, sh);
    float ss = block_sum(x0*x0 + x1*x1, sh);
    float m = s * (1.f/512.f);
    float r = rsqrtf(ss * (1.f/512.f) - m*m + 1e-6f);
    float* q = Y + row * E_;
    q[tid]     = (x0 - m) * r * gamma[g*E_+tid]     + beta[g*E_+tid];
    q[tid+256] = (x1 - m) * r * gamma[g*E_+tid+256] + beta[g*E_+tid+256];
}

// ---------------- instance-norm stats over [196,784] per z ----------------
__global__ void __launch_bounds__(256) inorm_stats_kernel(
    const float* __restrict__ attn, float* __restrict__ mean, float* __restrict__ rstd)
{
    __shared__ float sh[32];
    int z = blockIdx.x;
    const float* p = attn + (long long)z * ATTZ_;
    float s = 0.f, ss = 0.f;
    for (int i = threadIdx.x; i < ATTZ_; i += 256) {
        float v = p[i]; s += v; ss += v*v;
    }
    s  = block_sum(s, sh);
    ss = block_sum(ss, sh);
    if (threadIdx.x == 0) {
        float m = s * (1.f/(float)ATTZ_);
        float var = ss * (1.f/(float)ATTZ_) - m*m;
        mean[z] = m;
        rstd[z] = rsqrtf(var + 1e-5f);
    }
}

// ---------------- softmax (optional pre-normalization) ----------------
__global__ void __launch_bounds__(256) softmax_kernel(
    float* __restrict__ S, int cols, int rowsPerZ,
    const float* __restrict__ mean, const float* __restrict__ rstd, float scale)
{
    __shared__ float sh[32];
    long long row = blockIdx.x;
    float* p = S + row * cols;
    float m = 0.f, r = 1.f;
    if (mean) { int z = (int)(row / rowsPerZ); m = mean[z]; r = rstd[z]; }
    int tid = threadIdx.x;
    float vals[4];
    float mx = -INFINITY;
    int cnt = 0;
    for (int i = tid; i < cols; i += 256) {
        float t = mean ? (p[i] - m) * r : p[i] * scale;
        vals[cnt++] = t;
        mx = fmaxf(mx, t);
    }
    mx = block_max(mx, sh);
    float s = 0.f; cnt = 0;
    for (int i = tid; i < cols; i += 256) {
        float e = expf(vals[cnt] - mx);
        vals[cnt++] = e;
        s += e;
    }
    s = block_sum(s, sh);
    float inv = 1.f / s;
    cnt = 0;
    for (int i = tid; i < cols; i += 256) p[i] = vals[cnt++] * inv;
}

// ---------------- small elementwise kernels ----------------
__global__ void transpose_kernel(const float* __restrict__ in, float* __restrict__ out,
                                 int R, int Cc, int batch) {
    long long idx = (long long)blockIdx.x * blockDim.x + threadIdx.x;
    long long total = (long long)batch * R * Cc;
    if (idx >= total) return;
    int b = (int)(idx / ((long long)R*Cc));
    int rem = (int)(idx % ((long long)R*Cc));
    int r = rem / Cc, c = rem % Cc;
    out[(long long)b*R*Cc + (long long)c*R + r] = in[idx];
}

__global__ void reshape_kvs_kernel(const float* __restrict__ that, float* __restrict__ kvs) {
    int idx = blockIdx.x * blockDim.x + threadIdx.x;
    if (idx >= B_*FN_*E_) return;
    int b = idx / FNE_;
    int rem = idx % FNE_;
    int mrow = rem / E_;
    int e = rem % E_;
    int g = mrow / N_, n = mrow % N_;
    kvs[idx] = that[(long long)b*(N_*C_) + (long long)n*C_ + g*E_ + e];
}

__global__ void merge0_kernel(const float* __restrict__ ctx, float* __restrict__ cm0) {
    int idx = blockIdx.x * blockDim.x + threadIdx.x;
    if (idx >= BN_*E_) return;
    int b = idx / NE_;
    int rem = idx % NE_;
    int n = rem / E_;
    int e = rem % E_;
    int h = e >> 6, d = e & 63;
    cm0[idx] = ctx[((long long)(b*H_ + h)*N_ + n)*HD_ + d];
}

// ---------------- SGEMM NN: C = alpha*A@B (+bias)(+gelu)(+res) ----------------
__global__ void __launch_bounds__(256) gemm_nn(
    int M, int Ncol, int K,
    const float* __restrict__ A, int lda,
    const float* __restrict__ B, int ldb,
    float* __restrict__ C, int ldc,
    const float* __restrict__ bias,
    const float* __restrict__ res,
    int act, float alpha,
    int D0, int D1,
    long long sA0, long long sA1, long long sA2,
    long long sB0, long long sB1, long long sB2,
    long long sC0, long long sC1, long long sC2,
    long long sBias0, long long sBias1, long long sBias2,
    long long sR0, long long sR1, long long sR2)
{
    long long z = blockIdx.z;
    int z0 = (int)(z % D0); long long t = z / D0;
    int z1 = (int)(t % D1); int z2 = (int)(t / D1);
    A += z0*sA0 + z1*sA1 + z2*sA2;
    B += z0*sB0 + z1*sB1 + z2*sB2;
    C += z0*sC0 + z1*sC1 + z2*sC2;
    if (bias) bias += z0*sBias0 + z1*sBias1 + z2*sBias2;
    if (res)  res  += z0*sR0 + z1*sR1 + z2*sR2;

    __shared__ float As[8][128];
    __shared__ float Bs[8][128];
    int tid = threadIdx.x;
    int row0 = blockIdx.y * 128;
    int col0 = blockIdx.x * 128;
    int tx = tid & 15, ty = tid >> 4;
    float acc[8][8] = {};
    for (int k0 = 0; k0 < K; k0 += 8) {
        #pragma unroll
        for (int i = 0; i < 4; i++) {
            int idx = tid + i * 256;
            int r = idx >> 3, kk = idx & 7;
            int gr = row0 + r, gk = k0 + kk;
            As[kk][r] = (gr < M && gk < K) ? A[(long long)gr * lda + gk] : 0.f;
        }
        #pragma unroll
        for (int i = 0; i < 4; i++) {
            int idx = tid + i * 256;
            int kk = idx >> 7, cc = idx & 127;
            int gk = k0 + kk, gc = col0 + cc;
            Bs[kk][cc] = (gk < K && gc < Ncol) ? B[(long long)gk * ldb + gc] : 0.f;
        }
        __syncthreads();
        #pragma unroll
        for (int kk = 0; kk < 8; kk++) {
            float4 a0 = *(const float4*)&As[kk][ty * 8];
            float4 a1 = *(const float4*)&As[kk][ty * 8 + 4];
            float4 b0 = *(const float4*)&Bs[kk][tx * 8];
            float4 b1 = *(const float4*)&Bs[kk][tx * 8 + 4];
            float av[8] = {a0.x,a0.y,a0.z,a0.w,a1.x,a1.y,a1.z,a1.w};
            float bv[8] = {b0.x,b0.y,b0.z,b0.w,b1.x,b1.y,b1.z,b1.w};
            #pragma unroll
            for (int i = 0; i < 8; i++)
                #pragma unroll
                for (int j = 0; j < 8; j++)
                    acc[i][j] += av[i] * bv[j];
        }
        __syncthreads();
    }
    #pragma unroll
    for (int i = 0; i < 8; i++) {
        int gr = row0 + ty * 8 + i;
        if (gr >= M) continue;
        #pragma unroll
        for (int j = 0; j < 8; j++) {
            int gc = col0 + tx * 8 + j;
            if (gc >= Ncol) continue;
            float v = acc[i][j] * alpha;
            if (bias) v += bias[gc];
            if (act == 1) v = 0.5f * v * (1.f + erff(v * 0.70710678118654752f));
            if (res) v += res[(long long)gr * ldc + gc];
            C[(long long)gr * ldc + gc] = v;
        }
    }
}

// ---------------- SGEMM NT: C = alpha*A@B^T  (A:MxK lda, B:NxK ldb) ----------------
__global__ void __launch_bounds__(256) gemm_nt(
    int M, int Ncol, int K,
    const float* __restrict__ A, int lda,
    const float* __restrict__ B, int ldb,
    float* __restrict__ C, int ldc,
    float alpha,
    int D0, int D1,
    long long sA0, long long sA1, long long sA2,
    long long sB0, long long sB1, long long sB2,
    long long sC0, long long sC1, long long sC2)
{
    long long z = blockIdx.z;
    int z0 = (int)(z % D0); long long t = z / D0;
    int z1 = (int)(t % D1); int z2 = (int)(t / D1);
    A += z0*sA0 + z1*sA1 + z2*sA2;
    B += z0*sB0 + z1*sB1 + z2*sB2;
    C += z0*sC0 + z1*sC1 + z2*sC2;

    __shared__ float As[8][128];
    __shared__ float Bs[8][128];
    int tid = threadIdx.x;
    int row0 = blockIdx.y * 128;
    int col0 = blockIdx.x * 128;
    int tx = tid & 15, ty = tid >> 4;
    float acc[8][8] = {};
    for (int k0 = 0; k0 < K; k0 += 8) {
        #pragma unroll
        for (int i = 0; i < 4; i++) {
            int idx = tid + i * 256;
            int r = idx >> 3, kk = idx & 7;
            int gr = row0 + r, gk = k0 + kk;
            As[kk][r] = (gr < M && gk < K) ? A[(long long)gr * lda + gk] : 0.f;
        }
        #pragma unroll
        for (int i = 0; i < 4; i++) {
            int idx = tid + i * 256;
            int cc = idx >> 3, kk = idx & 7;
            int gk = k0 + kk, gc = col0 + cc;
            Bs[kk][cc] = (gk < K && gc < Ncol) ? B[(long long)gc * ldb + gk] : 0.f;
        }
        __syncthreads();
        #pragma unroll
        for (int kk = 0; kk < 8; kk++) {
            float4 a0 = *(const float4*)&As[kk][ty * 8];
            float4 a1 = *(const float4*)&As[kk][ty * 8 + 4];
            float4 b0 = *(const float4*)&Bs[kk][tx * 8];
            float4 b1 = *(const float4*)&Bs[kk][tx * 8 + 4];
            float av[8] = {a0.x,a0.y,a0.z,a0.w,a1.x,a1.y,a1.z,a1.w};
            float bv[8] = {b0.x,b0.y,b0.z,b0.w,b1.x,b1.y,b1.z,b1.w};
            #pragma unroll
            for (int i = 0; i < 8; i++)
                #pragma unroll
                for (int j = 0; j < 8; j++)
                    acc[i][j] += av[i] * bv[j];
        }
        __syncthreads();
    }
    #pragma unroll
    for (int i = 0; i < 8; i++) {
        int gr = row0 + ty * 8 + i;
        if (gr >= M) continue;
        #pragma unroll
        for (int j = 0; j < 8; j++) {
            int gc = col0 + tx * 8 + j;
            if (gc >= Ncol) continue;
            C[(long long)gr * ldc + gc] = acc[i][j] * alpha;
        }
    }
}

// ---------------- host launch ----------------
static float* symaddr(const void* sym) {
    void* p = nullptr;
    cudaGetSymbolAddress(&p, sym);
    return (float*)p;
}

extern "C" void kernel_launch(void* const* d_in, const int* in_sizes, int n_in,
                              void* d_out, int out_size) {
    const float* emb[4] = {(const float*)d_in[0], (const float*)d_in[1],
                           (const float*)d_in[2], (const float*)d_in[3]};
    const float* lag  = (const float*)d_in[4];
    const float* lab  = (const float*)d_in[5];
    const float* lcg  = (const float*)d_in[6];
    const float* lcb  = (const float*)d_in[7];
    const float* Wq   = (const float*)d_in[8];
    const float* Wk   = (const float*)d_in[9];
    const float* Wv   = (const float*)d_in[10];
    const float* Wo   = (const float*)d_in[11];
    const float* q_w  = (const float*)d_in[12];
    const float* k_w  = (const float*)d_in[13];
    const float* v_w  = (const float*)d_in[14];
    const float* outw = (const float*)d_in[15];
    const float* lfg  = (const float*)d_in[16];
    const float* lfb  = (const float*)d_in[17];
    const float* fc1w = (const float*)d_in[18];
    const float* fc1b = (const float*)d_in[19];
    const float* fc2w = (const float*)d_in[20];
    const float* fc2b = (const float*)d_in[21];
    float* out = (float*)d_out;

    float* cx   = symaddr(g_cx);
    float* ec   = symaddr(g_ec);
    float* qc   = symaddr(g_qc);
    float* kc   = symaddr(g_kc);
    float* vc   = symaddr(g_vc);
    float* sch  = symaddr(g_sch);
    float* tbuf = symaddr(g_t);
    float* that = symaddr(g_that);
    float* kvs  = symaddr(g_kvs);
    float* Qb   = symaddr(g_Q);
    float* Kb   = symaddr(g_K);
    float* Vb   = symaddr(g_V);
    float* attn = symaddr(g_attn);
    float* meanp= symaddr(g_mean);
    float* rstdp= symaddr(g_rstd);
    float* ctx  = symaddr(g_ctx);
    float* cm0  = symaddr(g_cm0);
    float* hbuf = symaddr(g_h);
    float* xln  = symaddr(g_xln);
    float* x1   = symaddr(g_x1);
    float* qwT  = symaddr(g_qwT);
    float* kwT  = symaddr(g_kwT);
    float* vwT  = symaddr(g_vwT);

    const long long Z = 0;

    // 1. fused LayerNorms
    ln_fused_kernel<<<BN_, 256>>>(emb[0], emb[1], emb[2], emb[3],
                                  lag, lab, lcg, lcb, cx, ec);

    // 2. transpose token-mixing weights
    transpose_kernel<<<(4*N_*N_ + 255)/256, 256>>>(q_w, qwT, N_, N_, 4);
    transpose_kernel<<<(FN_*FN_ + 255)/256, 256>>>(k_w, kwT, FN_, FN_, 1);
    transpose_kernel<<<(FN_*FN_ + 255)/256, 256>>>(v_w, vwT, FN_, FN_, 1);

    // 3. channel projections q,k,v = ec @ W   [3136,2048,2048]
    {
        dim3 g(16, 25, 1);
        gemm_nn<<<g,256>>>(BN_, C_, C_, ec, C_, Wq, C_, qc, C_, nullptr, nullptr, 0, 1.f,
                           1,1, Z,Z,Z, Z,Z,Z, Z,Z,Z, Z,Z,Z, Z,Z,Z);
        gemm_nn<<<g,256>>>(BN_, C_, C_, ec, C_, Wk, C_, kc, C_, nullptr, nullptr, 0, 1.f,
                           1,1, Z,Z,Z, Z,Z,Z, Z,Z,Z, Z,Z,Z, Z,Z,Z);
        gemm_nn<<<g,256>>>(BN_, C_, C_, ec, C_, Wv, C_, vc, C_, nullptr, nullptr, 0, 1.f,
                           1,1, Z,Z,Z, Z,Z,Z, Z,Z,Z, Z,Z,Z, Z,Z,Z);
    }

    // 4. channel attention scores: per (b,h)  [196,196,256]  alpha = 1/sqrt(256)
    {
        dim3 g(2, 2, B_*H_);
        gemm_nt<<<g,256>>>(N_, N_, HDC_, qc, C_, kc, C_, sch, N_, 0.0625f,
                           H_, B_,
                           256LL, (long long)N_*C_, Z,
                           256LL, (long long)N_*C_, Z,
                           (long long)SCHZ_, (long long)H_*SCHZ_, Z);
    }

    // 5. channel softmax over 196
    softmax_kernel<<<B_*H_*N_, 256>>>(sch, N_, 1, nullptr, nullptr, 1.f);

    // 6. T = s @ v  per (b,h) -> [B,N,C]
    {
        dim3 g(2, 2, B_*H_);
        gemm_nn<<<g,256>>>(N_, HDC_, N_, sch, N_, vc, C_, tbuf, C_, nullptr, nullptr, 0, 1.f,
                           H_, B_,
                           (long long)SCHZ_, (long long)H_*SCHZ_, Z,
                           256LL, (long long)N_*C_, Z,
                           256LL, (long long)N_*C_, Z,
                           Z,Z,Z, Z,Z,Z);
    }

    // 7. T_hat = T @ Wo
    {
        dim3 g(16, 25, 1);
        gemm_nn<<<g,256>>>(BN_, C_, C_, tbuf, C_, Wo, C_, that, C_, nullptr, nullptr, 0, 1.f,
                           1,1, Z,Z,Z, Z,Z,Z, Z,Z,Z, Z,Z,Z, Z,Z,Z);
    }

    // 8. KV_S reshape
    reshape_kvs_kernel<<<(B_*FN_*E_ + 255)/256, 256>>>(that, kvs);

    // 9. K = kwT @ KV_S, V = vwT @ KV_S  per batch b  [784,512,784]
    {
        dim3 g(4, 7, B_);
        gemm_nn<<<g,256>>>(FN_, E_, FN_, kwT, FN_, kvs, E_, Kb, E_, nullptr, nullptr, 0, 1.f,
                           B_, 1,
                           Z,Z,Z,
                           (long long)FNE_, Z, Z,
                           (long long)FNE_, Z, Z,
                           Z,Z,Z, Z,Z,Z);
        gemm_nn<<<g,256>>>(FN_, E_, FN_, vwT, FN_, kvs, E_, Vb, E_, nullptr, nullptr, 0, 1.f,
                           B_, 1,
                           Z,Z,Z,
                           (long long)FNE_, Z, Z,
                           (long long)FNE_, Z, Z,
                           Z,Z,Z, Z,Z,Z);
    }

    // 10. Q = qwT[g] @ cx[g,b]  per (g,b)  [196,512,196]
    {
        dim3 g(4, 2, 4*B_);
        gemm_nn<<<g,256>>>(N_, E_, N_, qwT, N_, cx, E_, Qb, E_, nullptr, nullptr, 0, 1.f,
                           B_, 4,
                           Z, (long long)SCHZ_, Z,
                           (long long)NE_, (long long)BNE_, Z,
                           (long long)NE_, (long long)BNE_, Z,
                           Z,Z,Z, Z,Z,Z);
    }

    // 11. spatial logits: per (g,b,h)  [196,784,64]
    {
        dim3 g(7, 2, 512);
        gemm_nt<<<g,256>>>(N_, FN_, HD_, Qb, E_, Kb, E_, attn, FN_, 1.f,
                           H_, B_,
                           64LL, (long long)NE_,  (long long)BNE_,
                           64LL, (long long)FNE_, Z,
                           (long long)ATTZ_, (long long)H_*ATTZ_, (long long)B_*H_*ATTZ_);
    }

    // 12. instance-norm stats per (g,b,h)
    inorm_stats_kernel<<<512, 256>>>(attn, meanp, rstdp);

    // 13. normalized softmax over 784
    softmax_kernel<<<512*N_, 256>>>(attn, FN_, N_, meanp, rstdp, 1.f);

    // 14. ctx = p @ Vh  per (g,b,h)  [196,64,784]
    {
        dim3 g(1, 2, 512);
        gemm_nn<<<g,256>>>(N_, HD_, FN_, attn, FN_, Vb, E_, ctx, HD_, nullptr, nullptr, 0, 1.f,
                           H_, B_,
                           (long long)ATTZ_, (long long)H_*ATTZ_, (long long)B_*H_*ATTZ_,
                           64LL, (long long)FNE_, Z,
                           (long long)(N_*HD_), (long long)(H_*N_*HD_), (long long)(B_*H_*N_*HD_),
                           Z,Z,Z, Z,Z,Z);
    }

    // 15. branch-0 head permute
    merge0_kernel<<<(BN_*E_ + 255)/256, 256>>>(ctx, cm0);

    // 16. out projection + residual-1:  h[g] = emb[g] + cmerged[g] @ out_w[g]
    {
        dim3 g(4, 25, 1);
        for (int gg = 0; gg < 4; gg++) {
            const float* Ag = (gg == 0) ? cm0 : (ctx + (long long)gg * BNE_);
            gemm_nn<<<g,256>>>(BN_, E_, E_, Ag, E_, outw + (long long)gg*E_*E_, E_,
                               hbuf + (long long)gg*BNE_, E_,
                               nullptr, emb[gg], 0, 1.f,
                               1,1, Z,Z,Z, Z,Z,Z, Z,Z,Z, Z,Z,Z, Z,Z,Z);
        }
    }

    // 17. FFN LayerNorm
    ln_rows_kernel<<<4*BN_, 256>>>(hbuf, lfg, lfb, xln, BN_);

    // 18. fc1 + bias + exact GELU  per g  [3136,2048,512]
    {
        dim3 g(16, 25, 4);
        gemm_nn<<<g,256>>>(BN_, 4*E_, E_, xln, E_, fc1w, 4*E_, x1, 4*E_,
                           fc1b, nullptr, 1, 1.f,
                           4, 1,
                           (long long)BNE_, Z, Z,
                           (long long)E_*4*E_, Z, Z,
                           (long long)BN_*4*E_, Z, Z,
                           (long long)4*E_, Z, Z,
                           Z,Z,Z);
    }

    // 19. fc2 + bias + residual-2 -> output  per g  [3136,512,2048]
    {
        dim3 g(4, 25, 4);
        gemm_nn<<<g,256>>>(BN_, E_, 4*E_, x1, 4*E_, fc2w, E_, out, E_,
                           fc2b, hbuf, 0, 1.f,
                           4, 1,
                           (long long)BN_*4*E_, Z, Z,
                           (long long)4*E_*E_, Z, Z,
                           (long long)BNE_, Z, Z,
                           (long long)E_, Z, Z,
                           (long long)BNE_, Z, Z);
    }
}

// round 4
// speedup vs baseline: 3.8260x; 3.8260x over previous
#include <cuda_runtime.h>
#include <cstdint>
#include <math.h>

#define B_     16
#define N_     196
#define E_     512
#define H_     8
#define HD_    64
#define C_     2048
#define HDC_   256
#define FN_    784
#define BN_    3136
#define NE_    100352
#define FNE_   401408
#define BNE_   1605632
#define SCHZ_  38416
#define ATTZ_  153664

// ---------------- scratch ----------------
__device__ __align__(128) float g_cx  [4*BN_*E_];
__device__ __align__(128) float g_cxT [4*B_*E_*N_];
__device__ __align__(128) float g_ec  [BN_*C_];
__device__ __align__(128) float g_qc  [BN_*C_];
__device__ __align__(128) float g_kc  [BN_*C_];
__device__ __align__(128) float g_vc  [BN_*C_];
__device__ __align__(128) float g_vcT [B_*C_*N_];
__device__ __align__(128) float g_sch [B_*H_*N_*N_];
__device__ __align__(128) float g_t   [BN_*C_];
__device__ __align__(128) float g_that[BN_*C_];
__device__ __align__(128) float g_kvsT[B_*E_*FN_];
__device__ __align__(128) float g_K   [B_*FN_*E_];
__device__ __align__(128) float g_V   [B_*FN_*E_];
__device__ __align__(128) float g_VT  [B_*E_*FN_];
__device__ __align__(128) float g_Q   [4*BN_*E_];
__device__ __align__(128) float g_attn[512u*196*784];
__device__ __align__(128) float g_mean[512];
__device__ __align__(128) float g_rstd[512];
__device__ __align__(128) float g_ctx [4*B_*H_*N_*HD_];
__device__ __align__(128) float g_cm0 [BN_*E_];
__device__ __align__(128) float g_h   [4*BN_*E_];
__device__ __align__(128) float g_xln [4*BN_*E_];
__device__ __align__(128) float g_x1  [4*BN_*2048];
__device__ __align__(128) float g_qwT [4*N_*N_];
__device__ __align__(128) float g_kwT [FN_*FN_];
__device__ __align__(128) float g_vwT [FN_*FN_];
__device__ __align__(128) float g_WqT [C_*C_];
__device__ __align__(128) float g_WkT [C_*C_];
__device__ __align__(128) float g_WvT [C_*C_];
__device__ __align__(128) float g_WoT [C_*C_];
__device__ __align__(128) float g_outwT[4*E_*E_];
__device__ __align__(128) float g_fc1wT[4*2048*E_];
__device__ __align__(128) float g_fc2wT[4*E_*2048];

// ---------------- helpers ----------------
__device__ __forceinline__ float tf32r(float x) {
    uint32_t u; asm("cvt.rna.tf32.f32 %0, %1;" : "=r"(u) : "f"(x));
    return __uint_as_float(u);
}
__device__ __forceinline__ float4 cvt4(float4 w) {
    w.x = tf32r(w.x); w.y = tf32r(w.y); w.z = tf32r(w.z); w.w = tf32r(w.w);
    return w;
}
__device__ __forceinline__ void mma_tf32(float* d, const uint32_t* a, const uint32_t* b) {
    asm volatile(
        "mma.sync.aligned.m16n8k8.row.col.f32.tf32.tf32.f32 "
        "{%0,%1,%2,%3}, {%4,%5,%6,%7}, {%8,%9}, {%0,%1,%2,%3};"
        : "+f"(d[0]), "+f"(d[1]), "+f"(d[2]), "+f"(d[3])
        : "r"(a[0]), "r"(a[1]), "r"(a[2]), "r"(a[3]), "r"(b[0]), "r"(b[1]));
}
__device__ __forceinline__ float gelu_f(float v) {
    return 0.5f * v * (1.f + erff(v * 0.70710678118654752f));
}

// ---------------- reductions ----------------
__device__ __forceinline__ float block_sum(float v, float* sh) {
    int tid = threadIdx.x;
    #pragma unroll
    for (int o = 16; o > 0; o >>= 1) v += __shfl_down_sync(0xffffffffu, v, o);
    if ((tid & 31) == 0) sh[tid >> 5] = v;
    __syncthreads();
    if (tid < 32) {
        float t = (tid < (int)(blockDim.x >> 5)) ? sh[tid] : 0.f;
        #pragma unroll
        for (int o = 16; o > 0; o >>= 1) t += __shfl_down_sync(0xffffffffu, t, o);
        if (tid == 0) sh[0] = t;
    }
    __syncthreads();
    float r = sh[0];
    __syncthreads();
    return r;
}
__device__ __forceinline__ float block_max(float v, float* sh) {
    int tid = threadIdx.x;
    #pragma unroll
    for (int o = 16; o > 0; o >>= 1) v = fmaxf(v, __shfl_down_sync(0xffffffffu, v, o));
    if ((tid & 31) == 0) sh[tid >> 5] = v;
    __syncthreads();
    if (tid < 32) {
        float t = (tid < (int)(blockDim.x >> 5)) ? sh[tid] : -INFINITY;
        #pragma unroll
        for (int o = 16; o > 0; o >>= 1) t = fmaxf(t, __shfl_down_sync(0xffffffffu, t, o));
        if (tid == 0) sh[0] = t;
    }
    __syncthreads();
    float r = sh[0];
    __syncthreads();
    return r;
}

// ---------------- LN / softmax / misc ----------------
__global__ void __launch_bounds__(256) ln_fused_kernel(
    const float* __restrict__ e1, const float* __restrict__ e2,
    const float* __restrict__ e3, const float* __restrict__ e4,
    const float* __restrict__ lag, const float* __restrict__ lab,
    const float* __restrict__ lcg, const float* __restrict__ lcb,
    float* __restrict__ cx, float* __restrict__ ec)
{
    __shared__ float sh[32];
    int token = blockIdx.x;
    int tid = threadIdx.x;
    const float* es[4] = {e1, e2, e3, e4};
    float x[4][2], mg[4], rg[4];
    float stot = 0.f, sstot = 0.f;
    #pragma unroll
    for (int g = 0; g < 4; g++) {
        const float* p = es[g] + (long long)token * E_;
        x[g][0] = p[tid]; x[g][1] = p[tid + 256];
        float s  = block_sum(x[g][0] + x[g][1], sh);
        float ss = block_sum(x[g][0]*x[g][0] + x[g][1]*x[g][1], sh);
        float m = s * (1.f/512.f);
        float v = ss * (1.f/512.f) - m*m;
        mg[g] = m; rg[g] = rsqrtf(v + 1e-6f);
        stot += s; sstot += ss;
    }
    float m = stot * (1.f/2048.f);
    float r = rsqrtf(sstot * (1.f/2048.f) - m*m + 1e-6f);
    #pragma unroll
    for (int g = 0; g < 4; g++) {
        #pragma unroll
        for (int j = 0; j < 2; j++) {
            int e = tid + j*256;
            float xv = x[g][j];
            cx[((long long)g*BN_ + token)*E_ + e] = (xv - mg[g]) * rg[g] * lag[g*E_+e] + lab[g*E_+e];
            ec[(long long)token*C_ + g*E_ + e]    = (xv - m) * r * lcg[g*E_+e] + lcb[g*E_+e];
        }
    }
}

__global__ void __launch_bounds__(256) ln_rows_kernel(
    const float* __restrict__ X, const float* __restrict__ gamma,
    const float* __restrict__ beta, float* __restrict__ Y, int rowsPerG)
{
    __shared__ float sh[32];
    long long row = blockIdx.x;
    int tid = threadIdx.x;
    int g = (int)(row / rowsPerG);
    const float* p = X + row * E_;
    float x0 = p[tid], x1 = p[tid+256];
    float s  = block_sum(x0 + x1, sh);
    float ss = block_sum(x0*x0 + x1*x1, sh);
    float m = s * (1.f/512.f);
    float r = rsqrtf(ss * (1.f/512.f) - m*m + 1e-6f);
    float* q = Y + row * E_;
    q[tid]     = (x0 - m) * r * gamma[g*E_+tid]     + beta[g*E_+tid];
    q[tid+256] = (x1 - m) * r * gamma[g*E_+tid+256] + beta[g*E_+tid+256];
}

__global__ void __launch_bounds__(512) inorm_stats_kernel(
    const float* __restrict__ attn, float* __restrict__ mean, float* __restrict__ rstd)
{
    __shared__ float sh[32];
    int z = blockIdx.x;
    const float* p = attn + (long long)z * ATTZ_;
    float s = 0.f, ss = 0.f;
    for (int i = threadIdx.x; i < ATTZ_; i += 512) {
        float v = p[i]; s += v; ss += v*v;
    }
    s  = block_sum(s, sh);
    ss = block_sum(ss, sh);
    if (threadIdx.x == 0) {
        float m = s * (1.f/(float)ATTZ_);
        mean[z] = m;
        rstd[z] = rsqrtf(ss * (1.f/(float)ATTZ_) - m*m + 1e-5f);
    }
}

__global__ void __launch_bounds__(256) softmax_kernel(
    float* __restrict__ S, int cols, int rowsPerZ,
    const float* __restrict__ mean, const float* __restrict__ rstd, float scale)
{
    __shared__ float sh[32];
    long long row = blockIdx.x;
    float* p = S + row * cols;
    float m = 0.f, r = 1.f;
    if (mean) { int z = (int)(row / rowsPerZ); m = mean[z]; r = rstd[z]; }
    int tid = threadIdx.x;
    float vals[4];
    float mx = -INFINITY;
    int cnt = 0;
    for (int i = tid; i < cols; i += 256) {
        float t = mean ? (p[i] - m) * r : p[i] * scale;
        vals[cnt++] = t;
        mx = fmaxf(mx, t);
    }
    mx = block_max(mx, sh);
    float s = 0.f; cnt = 0;
    for (int i = tid; i < cols; i += 256) {
        float e = expf(vals[cnt] - mx);
        vals[cnt++] = e;
        s += e;
    }
    s = block_sum(s, sh);
    float inv = 1.f / s;
    cnt = 0;
    for (int i = tid; i < cols; i += 256) p[i] = vals[cnt++] * inv;
}

// ---------------- tiled transpose (batched) ----------------
__global__ void transpose_tiled(const float* __restrict__ in, float* __restrict__ out,
                                int R, int Cc)
{
    __shared__ float t[32][33];
    long long zb = (long long)blockIdx.z * R * Cc;
    const float* ip = in + zb;
    float* op = out + zb;
    int c0 = blockIdx.x*32, r0 = blockIdx.y*32;
    int x = threadIdx.x, y = threadIdx.y;
    #pragma unroll
    for (int j = 0; j < 32; j += 8) {
        int r = r0 + y + j, c = c0 + x;
        if (r < R && c < Cc) t[y+j][x] = ip[(long long)r*Cc + c];
    }
    __syncthreads();
    #pragma unroll
    for (int j = 0; j < 32; j += 8) {
        int c = c0 + y + j, r = r0 + x;
        if (r < R && c < Cc) op[(long long)c*R + r] = t[x][y+j];
    }
}

// kvsT[b][e][g*196+n] = that[b][n][g*512+e]
__global__ void kvsT_kernel(const float* __restrict__ that, float* __restrict__ kvsT)
{
    __shared__ float t[32][33];
    int g = blockIdx.z & 3, b = blockIdx.z >> 2;
    int n0 = blockIdx.y*32, e0 = blockIdx.x*32;
    const float* in = that + (long long)b*N_*C_ + g*E_;
    float* out = kvsT + (long long)b*E_*FN_ + g*N_;
    int x = threadIdx.x, y = threadIdx.y;
    #pragma unroll
    for (int j = 0; j < 32; j += 8) {
        int n = n0 + y + j;
        if (n < N_) t[y+j][x] = in[(long long)n*C_ + e0 + x];
    }
    __syncthreads();
    #pragma unroll
    for (int j = 0; j < 32; j += 8) {
        int n = n0 + x;
        if (n < N_) out[(long long)(e0+y+j)*FN_ + n] = t[x][y+j];
    }
}

__global__ void merge0_kernel(const float* __restrict__ ctx, float* __restrict__ cm0) {
    int idx = blockIdx.x * blockDim.x + threadIdx.x;
    if (idx >= BN_*E_) return;
    int b = idx / NE_;
    int rem = idx % NE_;
    int n = rem / E_;
    int e = rem % E_;
    int h = e >> 6, d = e & 63;
    cm0[idx] = ctx[((long long)(b*H_ + h)*N_ + n)*HD_ + d];
}

// ---------------- tf32 mma.sync GEMM: C = alpha*A@B^T (+bias)(+gelu)(+res) ----------------
// A: [M,K] row-major, B: [Ncol,K] row-major. Tile 128x128, Ktile 32. 256 thr, 8 warps (2m x 4n).
__device__ __forceinline__ void ld_half(const float* __restrict__ P, int ldp,
                                        int gr, int lim, int K, int k0, float4* v) {
    if (gr < lim && k0 + 16 <= K) {
        const float4* p = (const float4*)(P + (long long)gr*ldp + k0);
        #pragma unroll
        for (int j = 0; j < 4; j++) v[j] = p[j];
    } else {
        #pragma unroll
        for (int j = 0; j < 4; j++) {
            float x0=0.f,x1=0.f,x2=0.f,x3=0.f;
            int gk = k0 + j*4;
            if (gr < lim) {
                const float* p = P + (long long)gr*ldp;
                if (gk   < K) x0 = p[gk];
                if (gk+1 < K) x1 = p[gk+1];
                if (gk+2 < K) x2 = p[gk+2];
                if (gk+3 < K) x3 = p[gk+3];
            }
            v[j] = make_float4(x0,x1,x2,x3);
        }
    }
}

__device__ __forceinline__ void epi_store(
    float* __restrict__ C, const float* __restrict__ bias, const float* __restrict__ res,
    int ldc, int row, int gc, int M, int act, float alpha, float c0, float c1)
{
    if (row >= M) return;
    float2 v = make_float2(c0*alpha, c1*alpha);
    if (bias) { v.x += bias[gc]; v.y += bias[gc+1]; }
    if (act)  { v.x = gelu_f(v.x); v.y = gelu_f(v.y); }
    if (res)  { float2 rr = *(const float2*)(res + (long long)row*ldc + gc);
                v.x += rr.x; v.y += rr.y; }
    *(float2*)(C + (long long)row*ldc + gc) = v;
}

__global__ void __launch_bounds__(256) gemm_tc(
    int M, int Ncol, int K,
    const float* __restrict__ A, int lda,
    const float* __restrict__ B, int ldb,
    float* __restrict__ C, int ldc,
    const float* __restrict__ bias,
    const float* __restrict__ res,
    int act, float alpha,
    int D0, int D1,
    long long sA0, long long sA1, long long sA2,
    long long sB0, long long sB1, long long sB2,
    long long sC0, long long sC1, long long sC2,
    long long sBias0, long long sBias1, long long sBias2,
    long long sR0, long long sR1, long long sR2)
{
    long long z = blockIdx.z;
    int z0 = (int)(z % D0); long long t = z / D0;
    int z1 = (int)(t % D1); int z2 = (int)(t / D1);
    A += z0*sA0 + z1*sA1 + z2*sA2;
    B += z0*sB0 + z1*sB1 + z2*sB2;
    C += z0*sC0 + z1*sC1 + z2*sC2;
    if (bias) bias += z0*sBias0 + z1*sBias1 + z2*sBias2;
    if (res)  res  += z0*sR0 + z1*sR1 + z2*sR2;

    __shared__ float As[128*32];
    __shared__ float Bs[128*32];

    int tid = threadIdx.x;
    int lane = tid & 31;
    int wid = tid >> 5;
    int warp_m = wid & 1;
    int warp_n = wid >> 1;
    int row0 = blockIdx.y * 128;
    int col0 = blockIdx.x * 128;

    float acc[4][4][4];
    #pragma unroll
    for (int i = 0; i < 4; i++)
        #pragma unroll
        for (int j = 0; j < 4; j++)
            #pragma unroll
            for (int q = 0; q < 4; q++) acc[i][j][q] = 0.f;

    int r = tid >> 1;
    int kh = (tid & 1) << 4;
    uint32_t sw = (uint32_t)((r & 7) << 2);

    float4 va[4], vb[4];
    ld_half(A, lda, row0 + r, M,    K, kh, va);
    ld_half(B, ldb, col0 + r, Ncol, K, kh, vb);

    int KT = (K + 31) >> 5;
    int lr = lane >> 2;       // 0..7
    int lc = lane & 3;        // 0..3

    for (int kt = 0; kt < KT; kt++) {
        if (kt) __syncthreads();
        #pragma unroll
        for (int j = 0; j < 4; j++) {
            int col = (kh + j*4) ^ sw;
            *(float4*)&As[r*32 + col] = cvt4(va[j]);
            *(float4*)&Bs[r*32 + col] = cvt4(vb[j]);
        }
        __syncthreads();
        if (kt + 1 < KT) {
            ld_half(A, lda, row0 + r, M,    K, (kt+1)*32 + kh, va);
            ld_half(B, ldb, col0 + r, Ncol, K, (kt+1)*32 + kh, vb);
        }
        #pragma unroll
        for (int ks = 0; ks < 4; ks++) {
            int kk = ks*8 + lc;
            uint32_t af[4][4], bf[4][2];
            #pragma unroll
            for (int i = 0; i < 4; i++) {
                int m = warp_m*64 + i*16 + lr;
                int s = (m & 7) << 2;
                int c0 = kk ^ s, c1 = (kk + 4) ^ s;
                af[i][0] = __float_as_uint(As[m*32 + c0]);
                af[i][1] = __float_as_uint(As[(m+8)*32 + c0]);
                af[i][2] = __float_as_uint(As[m*32 + c1]);
                af[i][3] = __float_as_uint(As[(m+8)*32 + c1]);
            }
            #pragma unroll
            for (int j = 0; j < 4; j++) {
                int n = warp_n*32 + j*8 + lr;
                int s = (n & 7) << 2;
                bf[j][0] = __float_as_uint(Bs[n*32 + (kk ^ s)]);
                bf[j][1] = __float_as_uint(Bs[n*32 + ((kk+4) ^ s)]);
            }
            #pragma unroll
            for (int i = 0; i < 4; i++)
                #pragma unroll
                for (int j = 0; j < 4; j++)
                    mma_tf32(acc[i][j], af[i], bf[j]);
        }
    }

    // epilogue
    #pragma unroll
    for (int i = 0; i < 4; i++) {
        int gr = row0 + warp_m*64 + i*16 + lr;
        #pragma unroll
        for (int j = 0; j < 4; j++) {
            int gc = col0 + warp_n*32 + j*8 + lc*2;
            if (gc >= Ncol) continue;
            epi_store(C, bias, res, ldc, gr,   gc, M, act, alpha, acc[i][j][0], acc[i][j][1]);
            epi_store(C, bias, res, ldc, gr+8, gc, M, act, alpha, acc[i][j][2], acc[i][j][3]);
        }
    }
}

// ---------------- host ----------------
static float* symaddr(const void* sym) {
    void* p = nullptr;
    cudaGetSymbolAddress(&p, sym);
    return (float*)p;
}

extern "C" void kernel_launch(void* const* d_in, const int* in_sizes, int n_in,
                              void* d_out, int out_size) {
    const float* emb[4] = {(const float*)d_in[0], (const float*)d_in[1],
                           (const float*)d_in[2], (const float*)d_in[3]};
    const float* lag  = (const float*)d_in[4];
    const float* lab  = (const float*)d_in[5];
    const float* lcg  = (const float*)d_in[6];
    const float* lcb  = (const float*)d_in[7];
    const float* Wq   = (const float*)d_in[8];
    const float* Wk   = (const float*)d_in[9];
    const float* Wv   = (const float*)d_in[10];
    const float* Wo   = (const float*)d_in[11];
    const float* q_w  = (const float*)d_in[12];
    const float* k_w  = (const float*)d_in[13];
    const float* v_w  = (const float*)d_in[14];
    const float* outw = (const float*)d_in[15];
    const float* lfg  = (const float*)d_in[16];
    const float* lfb  = (const float*)d_in[17];
    const float* fc1w = (const float*)d_in[18];
    const float* fc1b = (const float*)d_in[19];
    const float* fc2w = (const float*)d_in[20];
    const float* fc2b = (const float*)d_in[21];
    float* out = (float*)d_out;

    float* cx   = symaddr(g_cx);   float* cxT  = symaddr(g_cxT);
    float* ec   = symaddr(g_ec);
    float* qc   = symaddr(g_qc);   float* kc   = symaddr(g_kc);
    float* vc   = symaddr(g_vc);   float* vcT  = symaddr(g_vcT);
    float* sch  = symaddr(g_sch);  float* tbuf = symaddr(g_t);
    float* that = symaddr(g_that); float* kvsT = symaddr(g_kvsT);
    float* Kb   = symaddr(g_K);    float* Vb   = symaddr(g_V);
    float* VT   = symaddr(g_VT);   float* Qb   = symaddr(g_Q);
    float* attn = symaddr(g_attn);
    float* meanp= symaddr(g_mean); float* rstdp= symaddr(g_rstd);
    float* ctx  = symaddr(g_ctx);  float* cm0  = symaddr(g_cm0);
    float* hbuf = symaddr(g_h);    float* xln  = symaddr(g_xln);
    float* x1   = symaddr(g_x1);
    float* qwT  = symaddr(g_qwT);  float* kwT  = symaddr(g_kwT);
    float* vwT  = symaddr(g_vwT);
    float* WqT  = symaddr(g_WqT);  float* WkT  = symaddr(g_WkT);
    float* WvT  = symaddr(g_WvT);  float* WoT  = symaddr(g_WoT);
    float* outwT= symaddr(g_outwT);
    float* fc1wT= symaddr(g_fc1wT);float* fc2wT= symaddr(g_fc2wT);

    const long long Z = 0;
    dim3 tb(32, 8);

    // 1. fused LayerNorms
    ln_fused_kernel<<<BN_, 256>>>(emb[0], emb[1], emb[2], emb[3], lag, lab, lcg, lcb, cx, ec);

    // 2. weight transposes
    transpose_tiled<<<dim3(64, 64, 1), tb>>>(Wq, WqT, C_, C_);
    transpose_tiled<<<dim3(64, 64, 1), tb>>>(Wk, WkT, C_, C_);
    transpose_tiled<<<dim3(64, 64, 1), tb>>>(Wv, WvT, C_, C_);
    transpose_tiled<<<dim3(64, 64, 1), tb>>>(Wo, WoT, C_, C_);
    transpose_tiled<<<dim3(7, 7, 4),   tb>>>(q_w, qwT, N_, N_);
    transpose_tiled<<<dim3(25, 25, 1), tb>>>(k_w, kwT, FN_, FN_);
    transpose_tiled<<<dim3(25, 25, 1), tb>>>(v_w, vwT, FN_, FN_);
    transpose_tiled<<<dim3(16, 16, 4), tb>>>(outw, outwT, E_, E_);
    transpose_tiled<<<dim3(64, 16, 4), tb>>>(fc1w, fc1wT, E_, 2048);
    transpose_tiled<<<dim3(16, 64, 4), tb>>>(fc2w, fc2wT, 2048, E_);
    transpose_tiled<<<dim3(16, 7, 64), tb>>>(cx, cxT, N_, E_);

    // 3. channel projections: [3136,2048,2048]
    {
        dim3 g(16, 25, 1);
        gemm_tc<<<g,256>>>(BN_, C_, C_, ec, C_, WqT, C_, qc, C_, nullptr, nullptr, 0, 1.f,
                           1,1, Z,Z,Z, Z,Z,Z, Z,Z,Z, Z,Z,Z, Z,Z,Z);
        gemm_tc<<<g,256>>>(BN_, C_, C_, ec, C_, WkT, C_, kc, C_, nullptr, nullptr, 0, 1.f,
                           1,1, Z,Z,Z, Z,Z,Z, Z,Z,Z, Z,Z,Z, Z,Z,Z);
        gemm_tc<<<g,256>>>(BN_, C_, C_, ec, C_, WvT, C_, vc, C_, nullptr, nullptr, 0, 1.f,
                           1,1, Z,Z,Z, Z,Z,Z, Z,Z,Z, Z,Z,Z, Z,Z,Z);
    }
    transpose_tiled<<<dim3(64, 7, 16), tb>>>(vc, vcT, N_, C_);

    // 4. channel scores per (h,b): [196,196,256], alpha 1/16
    {
        dim3 g(2, 2, B_*H_);
        gemm_tc<<<g,256>>>(N_, N_, HDC_, qc, C_, kc, C_, sch, N_, nullptr, nullptr, 0, 0.0625f,
                           H_, B_,
                           256LL, (long long)N_*C_, Z,
                           256LL, (long long)N_*C_, Z,
                           (long long)SCHZ_, (long long)H_*SCHZ_, Z,
                           Z,Z,Z, Z,Z,Z);
    }
    // 5. channel softmax
    softmax_kernel<<<B_*H_*N_, 256>>>(sch, N_, 1, nullptr, nullptr, 1.f);

    // 6. T = s @ v per (h,b): [196,256,196]
    {
        dim3 g(2, 2, B_*H_);
        gemm_tc<<<g,256>>>(N_, HDC_, N_, sch, N_, vcT, N_, tbuf, C_, nullptr, nullptr, 0, 1.f,
                           H_, B_,
                           (long long)SCHZ_, (long long)H_*SCHZ_, Z,
                           (long long)(256*N_), (long long)C_*N_, Z,
                           256LL, (long long)N_*C_, Z,
                           Z,Z,Z, Z,Z,Z);
    }
    // 7. T_hat = T @ Wo
    {
        dim3 g(16, 25, 1);
        gemm_tc<<<g,256>>>(BN_, C_, C_, tbuf, C_, WoT, C_, that, C_, nullptr, nullptr, 0, 1.f,
                           1,1, Z,Z,Z, Z,Z,Z, Z,Z,Z, Z,Z,Z, Z,Z,Z);
    }
    // 8. fused KV_S reshape + transpose
    kvsT_kernel<<<dim3(16, 7, 64), tb>>>(that, kvsT);

    // 9. K/V token-mix per b: [784,512,784]
    {
        dim3 g(4, 7, B_);
        gemm_tc<<<g,256>>>(FN_, E_, FN_, kwT, FN_, kvsT, FN_, Kb, E_, nullptr, nullptr, 0, 1.f,
                           B_, 1,
                           Z,Z,Z,
                           (long long)E_*FN_, Z, Z,
                           (long long)FNE_, Z, Z,
                           Z,Z,Z, Z,Z,Z);
        gemm_tc<<<g,256>>>(FN_, E_, FN_, vwT, FN_, kvsT, FN_, Vb, E_, nullptr, nullptr, 0, 1.f,
                           B_, 1,
                           Z,Z,Z,
                           (long long)E_*FN_, Z, Z,
                           (long long)FNE_, Z, Z,
                           Z,Z,Z, Z,Z,Z);
    }
    transpose_tiled<<<dim3(16, 25, 16), tb>>>(Vb, VT, FN_, E_);

    // 10. Q token-mix per (b,g): [196,512,196]
    {
        dim3 g(4, 2, 4*B_);
        gemm_tc<<<g,256>>>(N_, E_, N_, qwT, N_, cxT, N_, Qb, E_, nullptr, nullptr, 0, 1.f,
                           B_, 4,
                           Z, (long long)SCHZ_, Z,
                           (long long)(E_*N_), (long long)B_*E_*N_, Z,
                           (long long)NE_, (long long)BNE_, Z,
                           Z,Z,Z, Z,Z,Z);
    }
    // 11. spatial logits per (h,b,g): [196,784,64]
    {
        dim3 g(7, 2, 512);
        gemm_tc<<<g,256>>>(N_, FN_, HD_, Qb, E_, Kb, E_, attn, FN_, nullptr, nullptr, 0, 1.f,
                           H_, B_,
                           64LL, (long long)NE_,  (long long)BNE_,
                           64LL, (long long)FNE_, Z,
                           (long long)ATTZ_, (long long)H_*ATTZ_, (long long)B_*H_*ATTZ_,
                           Z,Z,Z, Z,Z,Z);
    }
    // 12-13. instance-norm + softmax
    inorm_stats_kernel<<<512, 512>>>(attn, meanp, rstdp);
    softmax_kernel<<<512*N_, 256>>>(attn, FN_, N_, meanp, rstdp, 1.f);

    // 14. ctx = p @ Vh per (h,b,g): [196,64,784]
    {
        dim3 g(1, 2, 512);
        gemm_tc<<<g,256>>>(N_, HD_, FN_, attn, FN_, VT, FN_, ctx, HD_, nullptr, nullptr, 0, 1.f,
                           H_, B_,
                           (long long)ATTZ_, (long long)H_*ATTZ_, (long long)B_*H_*ATTZ_,
                           (long long)(HD_*FN_), (long long)E_*FN_, Z,
                           (long long)(N_*HD_), (long long)(H_*N_*HD_), (long long)(B_*H_*N_*HD_),
                           Z,Z,Z, Z,Z,Z);
    }
    // 15. branch-0 head permute
    merge0_kernel<<<(BN_*E_ + 255)/256, 256>>>(ctx, cm0);

    // 16. out projection + residual-1
    {
        dim3 g(4, 25, 1);
        for (int gg = 0; gg < 4; gg++) {
            const float* Ag = (gg == 0) ? cm0 : (ctx + (long long)gg * BNE_);
            gemm_tc<<<g,256>>>(BN_, E_, E_, Ag, E_, outwT + (long long)gg*E_*E_, E_,
                               hbuf + (long long)gg*BNE_, E_,
                               nullptr, emb[gg], 0, 1.f,
                               1,1, Z,Z,Z, Z,Z,Z, Z,Z,Z, Z,Z,Z, Z,Z,Z);
        }
    }
    // 17. FFN LayerNorm
    ln_rows_kernel<<<4*BN_, 256>>>(hbuf, lfg, lfb, xln, BN_);

    // 18. fc1 + bias + GELU per g: [3136,2048,512]
    {
        dim3 g(16, 25, 4);
        gemm_tc<<<g,256>>>(BN_, 4*E_, E_, xln, E_, fc1wT, E_, x1, 4*E_,
                           fc1b, nullptr, 1, 1.f,
                           4, 1,
                           (long long)BNE_, Z, Z,
                           (long long)(2048*E_), Z, Z,
                           (long long)BN_*4*E_, Z, Z,
                           (long long)(4*E_), Z, Z,
                           Z,Z,Z);
    }
    // 19. fc2 + bias + residual-2 -> out per g: [3136,512,2048]
    {
        dim3 g(4, 25, 4);
        gemm_tc<<<g,256>>>(BN_, E_, 4*E_, x1, 4*E_, fc2wT, 4*E_, out, E_,
                           fc2b, hbuf, 0, 1.f,
                           4, 1,
                           (long long)BN_*4*E_, Z, Z,
                           (long long)(E_*2048), Z, Z,
                           (long long)BNE_, Z, Z,
                           (long long)E_, Z, Z,
                           (long long)BNE_, Z, Z);
    }
}

// round 5
// speedup vs baseline: 3.9533x; 1.0333x over previous
#include <cuda_runtime.h>
#include <cstdint>
#include <math.h>

#define B_     16
#define N_     196
#define E_     512
#define H_     8
#define HD_    64
#define C_     2048
#define HDC_   256
#define FN_    784
#define BN_    3136
#define NE_    100352
#define FNE_   401408
#define BNE_   1605632
#define SCHZ_  38416
#define ATTZ_  153664

// ---------------- scratch ----------------
__device__ __align__(128) float g_cx  [4*BN_*E_];
__device__ __align__(128) float g_cxT [4*B_*E_*N_];
__device__ __align__(128) float g_ec  [BN_*C_];
__device__ __align__(128) float g_qc  [BN_*C_];
__device__ __align__(128) float g_kc  [BN_*C_];
__device__ __align__(128) float g_vc  [BN_*C_];
__device__ __align__(128) float g_vcT [B_*C_*N_];
__device__ __align__(128) float g_sch [B_*H_*N_*N_];
__device__ __align__(128) float g_t   [BN_*C_];
__device__ __align__(128) float g_that[BN_*C_];
__device__ __align__(128) float g_kvsT[B_*E_*FN_];
__device__ __align__(128) float g_KV  [2*B_*FN_*E_];   // K then V
__device__ __align__(128) float g_VT  [B_*E_*FN_];
__device__ __align__(128) float g_Q   [4*BN_*E_];
__device__ __align__(128) float g_attn[512u*196*784];
__device__ __align__(128) float g_rstd[512];
__device__ __align__(128) float g_ctx [4*B_*H_*N_*HD_];
__device__ __align__(128) float g_cm0 [BN_*E_];
__device__ __align__(128) float g_h   [4*BN_*E_];
__device__ __align__(128) float g_xln [4*BN_*E_];
__device__ __align__(128) float g_x1  [4*BN_*2048];
__device__ __align__(128) float g_qwT [4*N_*N_];
__device__ __align__(128) float g_kvwT[2*FN_*FN_];     // kwT then vwT
__device__ __align__(128) float g_WqT [C_*C_];
__device__ __align__(128) float g_WkT [C_*C_];
__device__ __align__(128) float g_WvT [C_*C_];
__device__ __align__(128) float g_WoT [C_*C_];
__device__ __align__(128) float g_outwT[4*E_*E_];
__device__ __align__(128) float g_fc1wT[4*2048*E_];
__device__ __align__(128) float g_fc2wT[4*E_*2048];

// ---------------- helpers ----------------
__device__ __forceinline__ uint32_t smem_u32(const void* p) {
    uint32_t a;
    asm("{ .reg .u64 t; cvta.to.shared.u64 t, %1; cvt.u32.u64 %0, t; }" : "=r"(a) : "l"(p));
    return a;
}
__device__ __forceinline__ float tf32r(float x) {
    uint32_t u; asm("cvt.rna.tf32.f32 %0, %1;" : "=r"(u) : "f"(x));
    return __uint_as_float(u);
}
__device__ __forceinline__ void mma_tf32(float* d, const uint32_t* a, const uint32_t* b) {
    asm volatile(
        "mma.sync.aligned.m16n8k8.row.col.f32.tf32.tf32.f32 "
        "{%0,%1,%2,%3}, {%4,%5,%6,%7}, {%8,%9}, {%0,%1,%2,%3};"
        : "+f"(d[0]), "+f"(d[1]), "+f"(d[2]), "+f"(d[3])
        : "r"(a[0]), "r"(a[1]), "r"(a[2]), "r"(a[3]), "r"(b[0]), "r"(b[1]));
}
__device__ __forceinline__ float gelu_f(float v) {
    return 0.5f * v * (1.f + erff(v * 0.70710678118654752f));
}
__device__ __forceinline__ void cpa16(uint32_t dst, const float* src, int bytes) {
    asm volatile("cp.async.ca.shared.global [%0], [%1], 16, %2;"
                 :: "r"(dst), "l"(src), "r"(bytes) : "memory");
}
#define CP_COMMIT() asm volatile("cp.async.commit_group;" ::: "memory")
#define CP_WAIT1()  asm volatile("cp.async.wait_group 1;" ::: "memory")

// ---------------- reductions ----------------
__device__ __forceinline__ float block_sum(float v, float* sh) {
    int tid = threadIdx.x;
    #pragma unroll
    for (int o = 16; o > 0; o >>= 1) v += __shfl_down_sync(0xffffffffu, v, o);
    if ((tid & 31) == 0) sh[tid >> 5] = v;
    __syncthreads();
    if (tid < 32) {
        float t = (tid < (int)(blockDim.x >> 5)) ? sh[tid] : 0.f;
        #pragma unroll
        for (int o = 16; o > 0; o >>= 1) t += __shfl_down_sync(0xffffffffu, t, o);
        if (tid == 0) sh[0] = t;
    }
    __syncthreads();
    float r = sh[0];
    __syncthreads();
    return r;
}
__device__ __forceinline__ float block_max(float v, float* sh) {
    int tid = threadIdx.x;
    #pragma unroll
    for (int o = 16; o > 0; o >>= 1) v = fmaxf(v, __shfl_down_sync(0xffffffffu, v, o));
    if ((tid & 31) == 0) sh[tid >> 5] = v;
    __syncthreads();
    if (tid < 32) {
        float t = (tid < (int)(blockDim.x >> 5)) ? sh[tid] : -INFINITY;
        #pragma unroll
        for (int o = 16; o > 0; o >>= 1) t = fmaxf(t, __shfl_down_sync(0xffffffffu, t, o));
        if (tid == 0) sh[0] = t;
    }
    __syncthreads();
    float r = sh[0];
    __syncthreads();
    return r;
}

// ---------------- LN (outputs tf32-rounded) ----------------
__global__ void __launch_bounds__(256) ln_fused_kernel(
    const float* __restrict__ e1, const float* __restrict__ e2,
    const float* __restrict__ e3, const float* __restrict__ e4,
    const float* __restrict__ lag, const float* __restrict__ lab,
    const float* __restrict__ lcg, const float* __restrict__ lcb,
    float* __restrict__ cx, float* __restrict__ ec)
{
    __shared__ float sh[32];
    int token = blockIdx.x;
    int tid = threadIdx.x;
    const float* es[4] = {e1, e2, e3, e4};
    float x[4][2], mg[4], rg[4];
    float stot = 0.f, sstot = 0.f;
    #pragma unroll
    for (int g = 0; g < 4; g++) {
        const float* p = es[g] + (long long)token * E_;
        x[g][0] = p[tid]; x[g][1] = p[tid + 256];
        float s  = block_sum(x[g][0] + x[g][1], sh);
        float ss = block_sum(x[g][0]*x[g][0] + x[g][1]*x[g][1], sh);
        float m = s * (1.f/512.f);
        float v = ss * (1.f/512.f) - m*m;
        mg[g] = m; rg[g] = rsqrtf(v + 1e-6f);
        stot += s; sstot += ss;
    }
    float m = stot * (1.f/2048.f);
    float r = rsqrtf(sstot * (1.f/2048.f) - m*m + 1e-6f);
    #pragma unroll
    for (int g = 0; g < 4; g++) {
        #pragma unroll
        for (int j = 0; j < 2; j++) {
            int e = tid + j*256;
            float xv = x[g][j];
            cx[((long long)g*BN_ + token)*E_ + e] =
                tf32r((xv - mg[g]) * rg[g] * lag[g*E_+e] + lab[g*E_+e]);
            ec[(long long)token*C_ + g*E_ + e] =
                tf32r((xv - m) * r * lcg[g*E_+e] + lcb[g*E_+e]);
        }
    }
}

__global__ void __launch_bounds__(256) ln_rows_kernel(
    const float* __restrict__ X, const float* __restrict__ gamma,
    const float* __restrict__ beta, float* __restrict__ Y, int rowsPerG)
{
    __shared__ float sh[32];
    long long row = blockIdx.x;
    int tid = threadIdx.x;
    int g = (int)(row / rowsPerG);
    const float* p = X + row * E_;
    float x0 = p[tid], x1 = p[tid+256];
    float s  = block_sum(x0 + x1, sh);
    float ss = block_sum(x0*x0 + x1*x1, sh);
    float m = s * (1.f/512.f);
    float r = rsqrtf(ss * (1.f/512.f) - m*m + 1e-6f);
    float* q = Y + row * E_;
    q[tid]     = tf32r((x0 - m) * r * gamma[g*E_+tid]     + beta[g*E_+tid]);
    q[tid+256] = tf32r((x1 - m) * r * gamma[g*E_+tid+256] + beta[g*E_+tid+256]);
}

// ---------------- instance-norm rstd over [196,784] per z ----------------
__global__ void __launch_bounds__(512) inorm_stats_kernel(
    const float* __restrict__ attn, float* __restrict__ rstd)
{
    __shared__ float sh[32];
    int z = blockIdx.x;
    const float* p = attn + (long long)z * ATTZ_;
    float s = 0.f, ss = 0.f;
    for (int i = threadIdx.x; i < ATTZ_; i += 512) {
        float v = p[i]; s += v; ss += v*v;
    }
    s  = block_sum(s, sh);
    ss = block_sum(ss, sh);
    if (threadIdx.x == 0) {
        float m = s * (1.f/(float)ATTZ_);
        rstd[z] = rsqrtf(ss * (1.f/(float)ATTZ_) - m*m + 1e-5f);
    }
}

// ---------------- softmax, fixed trip count, tf32-rounded output ----------------
// mean shift cancels inside softmax, so only rstd scaling is applied.
template<int NIT, bool PERZ>
__global__ void __launch_bounds__(256) softmax_fix(
    float* __restrict__ S, int cols, int rowsPerZ,
    const float* __restrict__ rstd, float scale)
{
    __shared__ float sh[32];
    long long row = blockIdx.x;
    float* p = S + row * cols;
    float sc = PERZ ? rstd[(int)(row / rowsPerZ)] : scale;
    int tid = threadIdx.x;
    float vals[NIT];
    float mx = -INFINITY;
    #pragma unroll
    for (int it = 0; it < NIT; it++) {
        int i = tid + it*256;
        float t = (i < cols) ? p[i]*sc : -INFINITY;
        vals[it] = t;
        mx = fmaxf(mx, t);
    }
    mx = block_max(mx, sh);
    float s = 0.f;
    #pragma unroll
    for (int it = 0; it < NIT; it++) {
        float e = expf(vals[it] - mx);
        vals[it] = e;
        s += e;
    }
    s = block_sum(s, sh);
    float inv = 1.f / s;
    #pragma unroll
    for (int it = 0; it < NIT; it++) {
        int i = tid + it*256;
        if (i < cols) p[i] = tf32r(vals[it] * inv);
    }
}

// ---------------- tiled transpose (batched, optional tf32 rounding) ----------------
__global__ void transpose_tiled(const float* __restrict__ in, float* __restrict__ out,
                                int R, int Cc, int doRound)
{
    __shared__ float t[32][33];
    long long zb = (long long)blockIdx.z * R * Cc;
    const float* ip = in + zb;
    float* op = out + zb;
    int c0 = blockIdx.x*32, r0 = blockIdx.y*32;
    int x = threadIdx.x, y = threadIdx.y;
    #pragma unroll
    for (int j = 0; j < 32; j += 8) {
        int r = r0 + y + j, c = c0 + x;
        if (r < R && c < Cc) {
            float v = ip[(long long)r*Cc + c];
            t[y+j][x] = doRound ? tf32r(v) : v;
        }
    }
    __syncthreads();
    #pragma unroll
    for (int j = 0; j < 32; j += 8) {
        int c = c0 + y + j, r = r0 + x;
        if (r < R && c < Cc) op[(long long)c*R + r] = t[x][y+j];
    }
}

// kvsT[b][e][g*196+n] = that[b][n][g*512+e]
__global__ void kvsT_kernel(const float* __restrict__ that, float* __restrict__ kvsT)
{
    __shared__ float t[32][33];
    int g = blockIdx.z & 3, b = blockIdx.z >> 2;
    int n0 = blockIdx.y*32, e0 = blockIdx.x*32;
    const float* in = that + (long long)b*N_*C_ + g*E_;
    float* out = kvsT + (long long)b*E_*FN_ + g*N_;
    int x = threadIdx.x, y = threadIdx.y;
    #pragma unroll
    for (int j = 0; j < 32; j += 8) {
        int n = n0 + y + j;
        if (n < N_) t[y+j][x] = in[(long long)n*C_ + e0 + x];
    }
    __syncthreads();
    #pragma unroll
    for (int j = 0; j < 32; j += 8) {
        int n = n0 + x;
        if (n < N_) out[(long long)(e0+y+j)*FN_ + n] = t[x][y+j];
    }
}

__global__ void merge0_kernel(const float* __restrict__ ctx, float* __restrict__ cm0) {
    int idx = blockIdx.x * blockDim.x + threadIdx.x;
    if (idx >= BN_*E_) return;
    int b = idx / NE_;
    int rem = idx % NE_;
    int n = rem / E_;
    int e = rem % E_;
    int h = e >> 6, d = e & 63;
    cm0[idx] = ctx[((long long)(b*H_ + h)*N_ + n)*HD_ + d];
}

// ---------------- tf32 mma.sync GEMM, cp.async double-buffered ----------------
// C = alpha*A@B^T (+bias)(+gelu)(+res)(optional tf32 round). A:[M,K], B:[Ncol,K] row-major.
// Inputs must already be tf32-rounded. Tile 128x128, Ktile 32, 256 thr (2x4 warps).
__device__ __forceinline__ void epi_store(
    float* __restrict__ C, const float* __restrict__ bias, const float* __restrict__ res,
    int ldc, int row, int gc, int M, int act, int roundC, float alpha, float c0, float c1)
{
    if (row >= M) return;
    float2 v = make_float2(c0*alpha, c1*alpha);
    if (bias) { v.x += bias[gc]; v.y += bias[gc+1]; }
    if (act)  { v.x = gelu_f(v.x); v.y = gelu_f(v.y); }
    if (res)  { float2 rr = *(const float2*)(res + (long long)row*ldc + gc);
                v.x += rr.x; v.y += rr.y; }
    if (roundC) { v.x = tf32r(v.x); v.y = tf32r(v.y); }
    *(float2*)(C + (long long)row*ldc + gc) = v;
}

__global__ void __launch_bounds__(256) gemm_tc(
    int M, int Ncol, int K,
    const float* __restrict__ A, int lda,
    const float* __restrict__ B, int ldb,
    float* __restrict__ C, int ldc,
    const float* __restrict__ bias,
    const float* __restrict__ res,
    int act, int roundC, float alpha,
    int D0, int D1,
    long long sA0, long long sA1, long long sA2,
    long long sB0, long long sB1, long long sB2,
    long long sC0, long long sC1, long long sC2,
    long long sBias0, long long sBias1, long long sBias2,
    long long sR0, long long sR1, long long sR2)
{
    long long z = blockIdx.z;
    int z0 = (int)(z % D0); long long t = z / D0;
    int z1 = (int)(t % D1); int z2 = (int)(t / D1);
    A += z0*sA0 + z1*sA1 + z2*sA2;
    B += z0*sB0 + z1*sB1 + z2*sB2;
    C += z0*sC0 + z1*sC1 + z2*sC2;
    if (bias) bias += z0*sBias0 + z1*sBias1 + z2*sBias2;
    if (res)  res  += z0*sR0 + z1*sR1 + z2*sR2;

    extern __shared__ float sm[];
    float* As = sm;            // [2][4096]
    float* Bs = sm + 8192;     // [2][4096]

    int tid = threadIdx.x;
    int lane = tid & 31;
    int wid = tid >> 5;
    int warp_m = wid & 1;
    int warp_n = wid >> 1;
    int row0 = blockIdx.y * 128;
    int col0 = blockIdx.x * 128;

    float acc[4][4][4];
    #pragma unroll
    for (int i = 0; i < 4; i++)
        #pragma unroll
        for (int j = 0; j < 4; j++)
            #pragma unroll
            for (int q = 0; q < 4; q++) acc[i][j][q] = 0.f;

    int r = tid >> 1;
    int kh = (tid & 1) << 4;
    uint32_t sw = (uint32_t)((r & 7) << 2);

    bool aval = (row0 + r) < M;
    bool bval = (col0 + r) < Ncol;
    const float* aRow = A + (long long)(aval ? row0 + r : 0) * lda;
    const float* bRow = B + (long long)(bval ? col0 + r : 0) * ldb;

    uint32_t aSm = smem_u32(As);
    uint32_t bSm = smem_u32(Bs);
    uint32_t dstOff[4];
    #pragma unroll
    for (int j = 0; j < 4; j++)
        dstOff[j] = (uint32_t)((r*32 + ((kh + j*4) ^ (int)sw)) << 2);

    int KT = (K + 31) >> 5;
    int lr = lane >> 2;
    int lc = lane & 3;

    // prologue: stage 0 into buffer 0
    {
        #pragma unroll
        for (int j = 0; j < 4; j++) {
            int gk = kh + j*4;
            int nb = (K - gk) * 4;
            nb = nb < 0 ? 0 : (nb > 16 ? 16 : nb);
            int ba = aval ? nb : 0;
            int bb = bval ? nb : 0;
            cpa16(aSm + dstOff[j], aRow + (ba ? gk : 0), ba);
            cpa16(bSm + dstOff[j], bRow + (bb ? gk : 0), bb);
        }
        CP_COMMIT();
    }

    for (int kt = 0; kt < KT; kt++) {
        int p = kt & 1;
        __syncthreads();   // WAR: all warps done reading buffer 1-p (MMA of kt-1)
        if (kt + 1 < KT) {
            uint32_t bo = (uint32_t)((1 - p) * 16384);
            #pragma unroll
            for (int j = 0; j < 4; j++) {
                int gk = (kt+1)*32 + kh + j*4;
                int nb = (K - gk) * 4;
                nb = nb < 0 ? 0 : (nb > 16 ? 16 : nb);
                int ba = aval ? nb : 0;
                int bb = bval ? nb : 0;
                cpa16(aSm + bo + dstOff[j], aRow + (ba ? gk : 0), ba);
                cpa16(bSm + bo + dstOff[j], bRow + (bb ? gk : 0), bb);
            }
        }
        CP_COMMIT();
        CP_WAIT1();
        __syncthreads();   // RAW: stage kt copies visible to all

        const float* Ab = As + p*4096;
        const float* Bb = Bs + p*4096;
        #pragma unroll
        for (int ks = 0; ks < 4; ks++) {
            int kk = ks*8 + lc;
            uint32_t af[4][4], bf[4][2];
            #pragma unroll
            for (int i = 0; i < 4; i++) {
                int m = warp_m*64 + i*16 + lr;
                int s = (m & 7) << 2;
                int c0 = kk ^ s, c1 = (kk + 4) ^ s;
                af[i][0] = __float_as_uint(Ab[m*32 + c0]);
                af[i][1] = __float_as_uint(Ab[(m+8)*32 + c0]);
                af[i][2] = __float_as_uint(Ab[m*32 + c1]);
                af[i][3] = __float_as_uint(Ab[(m+8)*32 + c1]);
            }
            #pragma unroll
            for (int j = 0; j < 4; j++) {
                int n = warp_n*32 + j*8 + lr;
                int s = (n & 7) << 2;
                bf[j][0] = __float_as_uint(Bb[n*32 + (kk ^ s)]);
                bf[j][1] = __float_as_uint(Bb[n*32 + ((kk+4) ^ s)]);
            }
            #pragma unroll
            for (int i = 0; i < 4; i++)
                #pragma unroll
                for (int j = 0; j < 4; j++)
                    mma_tf32(acc[i][j], af[i], bf[j]);
        }
    }

    #pragma unroll
    for (int i = 0; i < 4; i++) {
        int gr = row0 + warp_m*64 + i*16 + lr;
        #pragma unroll
        for (int j = 0; j < 4; j++) {
            int gc = col0 + warp_n*32 + j*8 + lc*2;
            if (gc >= Ncol) continue;
            epi_store(C, bias, res, ldc, gr,   gc, M, act, roundC, alpha, acc[i][j][0], acc[i][j][1]);
            epi_store(C, bias, res, ldc, gr+8, gc, M, act, roundC, alpha, acc[i][j][2], acc[i][j][3]);
        }
    }
}

// ---------------- host ----------------
static float* symaddr(const void* sym) {
    void* p = nullptr;
    cudaGetSymbolAddress(&p, sym);
    return (float*)p;
}

#define GSMEM 65536

extern "C" void kernel_launch(void* const* d_in, const int* in_sizes, int n_in,
                              void* d_out, int out_size) {
    const float* emb[4] = {(const float*)d_in[0], (const float*)d_in[1],
                           (const float*)d_in[2], (const float*)d_in[3]};
    const float* lag  = (const float*)d_in[4];
    const float* lab  = (const float*)d_in[5];
    const float* lcg  = (const float*)d_in[6];
    const float* lcb  = (const float*)d_in[7];
    const float* Wq   = (const float*)d_in[8];
    const float* Wk   = (const float*)d_in[9];
    const float* Wv   = (const float*)d_in[10];
    const float* Wo   = (const float*)d_in[11];
    const float* q_w  = (const float*)d_in[12];
    const float* k_w  = (const float*)d_in[13];
    const float* v_w  = (const float*)d_in[14];
    const float* outw = (const float*)d_in[15];
    const float* lfg  = (const float*)d_in[16];
    const float* lfb  = (const float*)d_in[17];
    const float* fc1w = (const float*)d_in[18];
    const float* fc1b = (const float*)d_in[19];
    const float* fc2w = (const float*)d_in[20];
    const float* fc2b = (const float*)d_in[21];
    float* out = (float*)d_out;

    cudaFuncSetAttribute(gemm_tc, cudaFuncAttributeMaxDynamicSharedMemorySize, GSMEM);

    float* cx   = symaddr(g_cx);   float* cxT  = symaddr(g_cxT);
    float* ec   = symaddr(g_ec);
    float* qc   = symaddr(g_qc);   float* kc   = symaddr(g_kc);
    float* vc   = symaddr(g_vc);   float* vcT  = symaddr(g_vcT);
    float* sch  = symaddr(g_sch);  float* tbuf = symaddr(g_t);
    float* that = symaddr(g_that); float* kvsT = symaddr(g_kvsT);
    float* KV   = symaddr(g_KV);   float* VT   = symaddr(g_VT);
    float* Qb   = symaddr(g_Q);    float* attn = symaddr(g_attn);
    float* rstdp= symaddr(g_rstd);
    float* ctx  = symaddr(g_ctx);  float* cm0  = symaddr(g_cm0);
    float* hbuf = symaddr(g_h);    float* xln  = symaddr(g_xln);
    float* x1   = symaddr(g_x1);
    float* qwT  = symaddr(g_qwT);  float* kvwT = symaddr(g_kvwT);
    float* WqT  = symaddr(g_WqT);  float* WkT  = symaddr(g_WkT);
    float* WvT  = symaddr(g_WvT);  float* WoT  = symaddr(g_WoT);
    float* outwT= symaddr(g_outwT);
    float* fc1wT= symaddr(g_fc1wT);float* fc2wT= symaddr(g_fc2wT);

    const long long Z = 0;
    dim3 tb(32, 8);

    // 1. fused LayerNorms (tf32-rounded outputs)
    ln_fused_kernel<<<BN_, 256>>>(emb[0], emb[1], emb[2], emb[3], lag, lab, lcg, lcb, cx, ec);

    // 2. weight transposes (rounded)
    transpose_tiled<<<dim3(64, 64, 1), tb>>>(Wq, WqT, C_, C_, 1);
    transpose_tiled<<<dim3(64, 64, 1), tb>>>(Wk, WkT, C_, C_, 1);
    transpose_tiled<<<dim3(64, 64, 1), tb>>>(Wv, WvT, C_, C_, 1);
    transpose_tiled<<<dim3(64, 64, 1), tb>>>(Wo, WoT, C_, C_, 1);
    transpose_tiled<<<dim3(7, 7, 4),   tb>>>(q_w, qwT, N_, N_, 1);
    transpose_tiled<<<dim3(25, 25, 1), tb>>>(k_w, kvwT, FN_, FN_, 1);
    transpose_tiled<<<dim3(25, 25, 1), tb>>>(v_w, kvwT + (long long)FN_*FN_, FN_, FN_, 1);
    transpose_tiled<<<dim3(16, 16, 4), tb>>>(outw, outwT, E_, E_, 1);
    transpose_tiled<<<dim3(64, 16, 4), tb>>>(fc1w, fc1wT, E_, 2048, 1);
    transpose_tiled<<<dim3(16, 64, 4), tb>>>(fc2w, fc2wT, 2048, E_, 1);
    transpose_tiled<<<dim3(16, 7, 64), tb>>>(cx, cxT, N_, E_, 0);

    // 3. channel projections: [3136,2048,2048] (rounded out)
    {
        dim3 g(16, 25, 1);
        gemm_tc<<<g,256,GSMEM>>>(BN_, C_, C_, ec, C_, WqT, C_, qc, C_, nullptr, nullptr, 0, 1, 1.f,
                           1,1, Z,Z,Z, Z,Z,Z, Z,Z,Z, Z,Z,Z, Z,Z,Z);
        gemm_tc<<<g,256,GSMEM>>>(BN_, C_, C_, ec, C_, WkT, C_, kc, C_, nullptr, nullptr, 0, 1, 1.f,
                           1,1, Z,Z,Z, Z,Z,Z, Z,Z,Z, Z,Z,Z, Z,Z,Z);
        gemm_tc<<<g,256,GSMEM>>>(BN_, C_, C_, ec, C_, WvT, C_, vc, C_, nullptr, nullptr, 0, 1, 1.f,
                           1,1, Z,Z,Z, Z,Z,Z, Z,Z,Z, Z,Z,Z, Z,Z,Z);
    }
    transpose_tiled<<<dim3(64, 7, 16), tb>>>(vc, vcT, N_, C_, 0);

    // 4. channel scores per (h,b): [196,196,256]
    {
        dim3 g(2, 2, B_*H_);
        gemm_tc<<<g,256,GSMEM>>>(N_, N_, HDC_, qc, C_, kc, C_, sch, N_, nullptr, nullptr, 0, 0, 0.0625f,
                           H_, B_,
                           256LL, (long long)N_*C_, Z,
                           256LL, (long long)N_*C_, Z,
                           (long long)SCHZ_, (long long)H_*SCHZ_, Z,
                           Z,Z,Z, Z,Z,Z);
    }
    // 5. channel softmax (196 cols)
    softmax_fix<1,false><<<B_*H_*N_, 256>>>(sch, N_, 1, nullptr, 1.f);

    // 6. T = s @ v per (h,b): [196,256,196]
    {
        dim3 g(2, 2, B_*H_);
        gemm_tc<<<g,256,GSMEM>>>(N_, HDC_, N_, sch, N_, vcT, N_, tbuf, C_, nullptr, nullptr, 0, 1, 1.f,
                           H_, B_,
                           (long long)SCHZ_, (long long)H_*SCHZ_, Z,
                           (long long)(256*N_), (long long)C_*N_, Z,
                           256LL, (long long)N_*C_, Z,
                           Z,Z,Z, Z,Z,Z);
    }
    // 7. T_hat = T @ Wo
    {
        dim3 g(16, 25, 1);
        gemm_tc<<<g,256,GSMEM>>>(BN_, C_, C_, tbuf, C_, WoT, C_, that, C_, nullptr, nullptr, 0, 1, 1.f,
                           1,1, Z,Z,Z, Z,Z,Z, Z,Z,Z, Z,Z,Z, Z,Z,Z);
    }
    // 8. fused KV_S reshape + transpose
    kvsT_kernel<<<dim3(16, 7, 64), tb>>>(that, kvsT);

    // 9. K/V token-mix merged: z=(which, b), [784,512,784]
    {
        dim3 g(4, 7, 2*B_);
        gemm_tc<<<g,256,GSMEM>>>(FN_, E_, FN_, kvwT, FN_, kvsT, FN_, KV, E_, nullptr, nullptr, 0, 1, 1.f,
                           2, B_,
                           (long long)FN_*FN_, Z, Z,
                           Z, (long long)E_*FN_, Z,
                           (long long)B_*FNE_, (long long)FNE_, Z,
                           Z,Z,Z, Z,Z,Z);
    }
    transpose_tiled<<<dim3(16, 25, 16), tb>>>(KV + (long long)B_*FNE_, VT, FN_, E_, 0);

    // 10. Q token-mix per (b,g): [196,512,196]
    {
        dim3 g(4, 2, 4*B_);
        gemm_tc<<<g,256,GSMEM>>>(N_, E_, N_, qwT, N_, cxT, N_, Qb, E_, nullptr, nullptr, 0, 1, 1.f,
                           B_, 4,
                           Z, (long long)SCHZ_, Z,
                           (long long)(E_*N_), (long long)B_*E_*N_, Z,
                           (long long)NE_, (long long)BNE_, Z,
                           Z,Z,Z, Z,Z,Z);
    }
    // 11. spatial logits per (h,b,g): [196,784,64]
    {
        dim3 g(7, 2, 512);
        gemm_tc<<<g,256,GSMEM>>>(N_, FN_, HD_, Qb, E_, KV, E_, attn, FN_, nullptr, nullptr, 0, 0, 1.f,
                           H_, B_,
                           64LL, (long long)NE_,  (long long)BNE_,
                           64LL, (long long)FNE_, Z,
                           (long long)ATTZ_, (long long)H_*ATTZ_, (long long)B_*H_*ATTZ_,
                           Z,Z,Z, Z,Z,Z);
    }
    // 12-13. instance-norm rstd + normalized softmax (784 cols)
    inorm_stats_kernel<<<512, 512>>>(attn, rstdp);
    softmax_fix<4,true><<<512*N_, 256>>>(attn, FN_, N_, rstdp, 1.f);

    // 14. ctx = p @ Vh per (h,b,g): [196,64,784]
    {
        dim3 g(1, 2, 512);
        gemm_tc<<<g,256,GSMEM>>>(N_, HD_, FN_, attn, FN_, VT, FN_, ctx, HD_, nullptr, nullptr, 0, 1, 1.f,
                           H_, B_,
                           (long long)ATTZ_, (long long)H_*ATTZ_, (long long)B_*H_*ATTZ_,
                           (long long)(HD_*FN_), (long long)E_*FN_, Z,
                           (long long)(N_*HD_), (long long)(H_*N_*HD_), (long long)(B_*H_*N_*HD_),
                           Z,Z,Z, Z,Z,Z);
    }
    // 15. branch-0 head permute
    merge0_kernel<<<(BN_*E_ + 255)/256, 256>>>(ctx, cm0);

    // 16. out projection + residual-1 (exact fp32 out)
    {
        dim3 g(4, 25, 1);
        for (int gg = 0; gg < 4; gg++) {
            const float* Ag = (gg == 0) ? cm0 : (ctx + (long long)gg * BNE_);
            gemm_tc<<<g,256,GSMEM>>>(BN_, E_, E_, Ag, E_, outwT + (long long)gg*E_*E_, E_,
                               hbuf + (long long)gg*BNE_, E_,
                               nullptr, emb[gg], 0, 0, 1.f,
                               1,1, Z,Z,Z, Z,Z,Z, Z,Z,Z, Z,Z,Z, Z,Z,Z);
        }
    }
    // 17. FFN LayerNorm
    ln_rows_kernel<<<4*BN_, 256>>>(hbuf, lfg, lfb, xln, BN_);

    // 18. fc1 + bias + GELU per g: [3136,2048,512] (rounded out)
    {
        dim3 g(16, 25, 4);
        gemm_tc<<<g,256,GSMEM>>>(BN_, 4*E_, E_, xln, E_, fc1wT, E_, x1, 4*E_,
                           fc1b, nullptr, 1, 1, 1.f,
                           4, 1,
                           (long long)BNE_, Z, Z,
                           (long long)(2048*E_), Z, Z,
                           (long long)BN_*4*E_, Z, Z,
                           (long long)(4*E_), Z, Z,
                           Z,Z,Z);
    }
    // 19. fc2 + bias + residual-2 -> out (exact fp32)
    {
        dim3 g(4, 25, 4);
        gemm_tc<<<g,256,GSMEM>>>(BN_, E_, 4*E_, x1, 4*E_, fc2wT, 4*E_, out, E_,
                           fc2b, hbuf, 0, 0, 1.f,
                           4, 1,
                           (long long)BN_*4*E_, Z, Z,
                           (long long)(E_*2048), Z, Z,
                           (long long)BNE_, Z, Z,
                           (long long)E_, Z, Z,
                           (long long)BNE_, Z, Z);
    }
}

// round 6
// speedup vs baseline: 3.9733x; 1.0051x over previous
#include <cuda_runtime.h>
#include <cstdint>
#include <math.h>

#define B_     16
#define N_     196
#define E_     512
#define H_     8
#define HD_    64
#define C_     2048
#define HDC_   256
#define FN_    784
#define BN_    3136
#define NE_    100352
#define FNE_   401408
#define BNE_   1605632
#define SCHZ_  38416
#define ATTZ_  153664

// ---------------- scratch ----------------
__device__ __align__(128) float g_cx  [4*BN_*E_];
__device__ __align__(128) float g_cxT [4*B_*E_*N_];
__device__ __align__(128) float g_ec  [BN_*C_];
__device__ __align__(128) float g_qc  [BN_*C_];
__device__ __align__(128) float g_kc  [BN_*C_];
__device__ __align__(128) float g_vc  [BN_*C_];
__device__ __align__(128) float g_vcT [B_*C_*N_];
__device__ __align__(128) float g_sch [B_*H_*N_*N_];
__device__ __align__(128) float g_t   [BN_*C_];
__device__ __align__(128) float g_that[BN_*C_];
__device__ __align__(128) float g_kvsT[B_*E_*FN_];
__device__ __align__(128) float g_KV  [2*B_*FN_*E_];   // K then V
__device__ __align__(128) float g_VT  [B_*E_*FN_];
__device__ __align__(128) float g_Q   [4*BN_*E_];
__device__ __align__(128) float g_attn[512u*196*784];
__device__ __align__(128) float g_rstd[512];
__device__ __align__(128) float g_ctx [4*B_*H_*N_*HD_];
__device__ __align__(128) float g_cm0 [BN_*E_];
__device__ __align__(128) float g_h   [4*BN_*E_];
__device__ __align__(128) float g_xln [4*BN_*E_];
__device__ __align__(128) float g_x1  [4*BN_*2048];
__device__ __align__(128) float g_qwT [4*N_*N_];
__device__ __align__(128) float g_kvwT[2*FN_*FN_];
__device__ __align__(128) float g_WqT [C_*C_];
__device__ __align__(128) float g_WkT [C_*C_];
__device__ __align__(128) float g_WvT [C_*C_];
__device__ __align__(128) float g_WoT [C_*C_];
__device__ __align__(128) float g_outwT[4*E_*E_];
__device__ __align__(128) float g_fc1wT[4*2048*E_];
__device__ __align__(128) float g_fc2wT[4*E_*2048];

// ---------------- helpers ----------------
__device__ __forceinline__ uint32_t smem_u32(const void* p) {
    uint32_t a;
    asm("{ .reg .u64 t; cvta.to.shared.u64 t, %1; cvt.u32.u64 %0, t; }" : "=r"(a) : "l"(p));
    return a;
}
__device__ __forceinline__ float tf32r(float x) {
    uint32_t u; asm("cvt.rna.tf32.f32 %0, %1;" : "=r"(u) : "f"(x));
    return __uint_as_float(u);
}
__device__ __forceinline__ void mma_tf32(float* d, const uint32_t* a, const uint32_t* b) {
    asm volatile(
        "mma.sync.aligned.m16n8k8.row.col.f32.tf32.tf32.f32 "
        "{%0,%1,%2,%3}, {%4,%5,%6,%7}, {%8,%9}, {%0,%1,%2,%3};"
        : "+f"(d[0]), "+f"(d[1]), "+f"(d[2]), "+f"(d[3])
        : "r"(a[0]), "r"(a[1]), "r"(a[2]), "r"(a[3]), "r"(b[0]), "r"(b[1]));
}
__device__ __forceinline__ float gelu_f(float v) {
    return 0.5f * v * (1.f + erff(v * 0.70710678118654752f));
}
__device__ __forceinline__ void cpa16(uint32_t dst, const float* src, int bytes) {
    asm volatile("cp.async.ca.shared.global [%0], [%1], 16, %2;"
                 :: "r"(dst), "l"(src), "r"(bytes) : "memory");
}
#define CP_COMMIT() asm volatile("cp.async.commit_group;" ::: "memory")
#define CP_WAIT1()  asm volatile("cp.async.wait_group 1;" ::: "memory")

// ---------------- reductions ----------------
__device__ __forceinline__ float block_sum(float v, float* sh) {
    int tid = threadIdx.x;
    #pragma unroll
    for (int o = 16; o > 0; o >>= 1) v += __shfl_down_sync(0xffffffffu, v, o);
    if ((tid & 31) == 0) sh[tid >> 5] = v;
    __syncthreads();
    if (tid < 32) {
        float t = (tid < (int)(blockDim.x >> 5)) ? sh[tid] : 0.f;
        #pragma unroll
        for (int o = 16; o > 0; o >>= 1) t += __shfl_down_sync(0xffffffffu, t, o);
        if (tid == 0) sh[0] = t;
    }
    __syncthreads();
    float r = sh[0];
    __syncthreads();
    return r;
}
__device__ __forceinline__ float block_max(float v, float* sh) {
    int tid = threadIdx.x;
    #pragma unroll
    for (int o = 16; o > 0; o >>= 1) v = fmaxf(v, __shfl_down_sync(0xffffffffu, v, o));
    if ((tid & 31) == 0) sh[tid >> 5] = v;
    __syncthreads();
    if (tid < 32) {
        float t = (tid < (int)(blockDim.x >> 5)) ? sh[tid] : -INFINITY;
        #pragma unroll
        for (int o = 16; o > 0; o >>= 1) t = fmaxf(t, __shfl_down_sync(0xffffffffu, t, o));
        if (tid == 0) sh[0] = t;
    }
    __syncthreads();
    float r = sh[0];
    __syncthreads();
    return r;
}

// ---------------- LN (outputs tf32-rounded) ----------------
__global__ void __launch_bounds__(256) ln_fused_kernel(
    const float* __restrict__ e1, const float* __restrict__ e2,
    const float* __restrict__ e3, const float* __restrict__ e4,
    const float* __restrict__ lag, const float* __restrict__ lab,
    const float* __restrict__ lcg, const float* __restrict__ lcb,
    float* __restrict__ cx, float* __restrict__ ec)
{
    __shared__ float sh[32];
    int token = blockIdx.x;
    int tid = threadIdx.x;
    const float* es[4] = {e1, e2, e3, e4};
    float x[4][2], mg[4], rg[4];
    float stot = 0.f, sstot = 0.f;
    #pragma unroll
    for (int g = 0; g < 4; g++) {
        const float* p = es[g] + (long long)token * E_;
        x[g][0] = p[tid]; x[g][1] = p[tid + 256];
        float s  = block_sum(x[g][0] + x[g][1], sh);
        float ss = block_sum(x[g][0]*x[g][0] + x[g][1]*x[g][1], sh);
        float m = s * (1.f/512.f);
        float v = ss * (1.f/512.f) - m*m;
        mg[g] = m; rg[g] = rsqrtf(v + 1e-6f);
        stot += s; sstot += ss;
    }
    float m = stot * (1.f/2048.f);
    float r = rsqrtf(sstot * (1.f/2048.f) - m*m + 1e-6f);
    #pragma unroll
    for (int g = 0; g < 4; g++) {
        #pragma unroll
        for (int j = 0; j < 2; j++) {
            int e = tid + j*256;
            float xv = x[g][j];
            cx[((long long)g*BN_ + token)*E_ + e] =
                tf32r((xv - mg[g]) * rg[g] * lag[g*E_+e] + lab[g*E_+e]);
            ec[(long long)token*C_ + g*E_ + e] =
                tf32r((xv - m) * r * lcg[g*E_+e] + lcb[g*E_+e]);
        }
    }
}

__global__ void __launch_bounds__(256) ln_rows_kernel(
    const float* __restrict__ X, const float* __restrict__ gamma,
    const float* __restrict__ beta, float* __restrict__ Y, int rowsPerG)
{
    __shared__ float sh[32];
    long long row = blockIdx.x;
    int tid = threadIdx.x;
    int g = (int)(row / rowsPerG);
    const float* p = X + row * E_;
    float x0 = p[tid], x1 = p[tid+256];
    float s  = block_sum(x0 + x1, sh);
    float ss = block_sum(x0*x0 + x1*x1, sh);
    float m = s * (1.f/512.f);
    float r = rsqrtf(ss * (1.f/512.f) - m*m + 1e-6f);
    float* q = Y + row * E_;
    q[tid]     = tf32r((x0 - m) * r * gamma[g*E_+tid]     + beta[g*E_+tid]);
    q[tid+256] = tf32r((x1 - m) * r * gamma[g*E_+tid+256] + beta[g*E_+tid+256]);
}

// ---------------- instance-norm rstd ----------------
__global__ void __launch_bounds__(512) inorm_stats_kernel(
    const float* __restrict__ attn, float* __restrict__ rstd)
{
    __shared__ float sh[32];
    int z = blockIdx.x;
    const float* p = attn + (long long)z * ATTZ_;
    float s = 0.f, ss = 0.f;
    for (int i = threadIdx.x; i < ATTZ_; i += 512) {
        float v = p[i]; s += v; ss += v*v;
    }
    s  = block_sum(s, sh);
    ss = block_sum(ss, sh);
    if (threadIdx.x == 0) {
        float m = s * (1.f/(float)ATTZ_);
        rstd[z] = rsqrtf(ss * (1.f/(float)ATTZ_) - m*m + 1e-5f);
    }
}

// ---------------- softmax ----------------
template<int NIT, bool PERZ>
__global__ void __launch_bounds__(256) softmax_fix(
    float* __restrict__ S, int cols, int rowsPerZ,
    const float* __restrict__ rstd, float scale)
{
    __shared__ float sh[32];
    long long row = blockIdx.x;
    float* p = S + row * cols;
    float sc = PERZ ? rstd[(int)(row / rowsPerZ)] : scale;
    int tid = threadIdx.x;
    float vals[NIT];
    float mx = -INFINITY;
    #pragma unroll
    for (int it = 0; it < NIT; it++) {
        int i = tid + it*256;
        float t = (i < cols) ? p[i]*sc : -INFINITY;
        vals[it] = t;
        mx = fmaxf(mx, t);
    }
    mx = block_max(mx, sh);
    float s = 0.f;
    #pragma unroll
    for (int it = 0; it < NIT; it++) {
        float e = expf(vals[it] - mx);
        vals[it] = e;
        s += e;
    }
    s = block_sum(s, sh);
    float inv = 1.f / s;
    #pragma unroll
    for (int it = 0; it < NIT; it++) {
        int i = tid + it*256;
        if (i < cols) p[i] = tf32r(vals[it] * inv);
    }
}

// ---------------- tiled transpose ----------------
__global__ void transpose_tiled(const float* __restrict__ in, float* __restrict__ out,
                                int R, int Cc, int doRound)
{
    __shared__ float t[32][33];
    long long zb = (long long)blockIdx.z * R * Cc;
    const float* ip = in + zb;
    float* op = out + zb;
    int c0 = blockIdx.x*32, r0 = blockIdx.y*32;
    int x = threadIdx.x, y = threadIdx.y;
    #pragma unroll
    for (int j = 0; j < 32; j += 8) {
        int r = r0 + y + j, c = c0 + x;
        if (r < R && c < Cc) {
            float v = ip[(long long)r*Cc + c];
            t[y+j][x] = doRound ? tf32r(v) : v;
        }
    }
    __syncthreads();
    #pragma unroll
    for (int j = 0; j < 32; j += 8) {
        int c = c0 + y + j, r = r0 + x;
        if (r < R && c < Cc) op[(long long)c*R + r] = t[x][y+j];
    }
}

// kvsT[b][e][g*196+n] = that[b][n][g*512+e]
__global__ void kvsT_kernel(const float* __restrict__ that, float* __restrict__ kvsT)
{
    __shared__ float t[32][33];
    int g = blockIdx.z & 3, b = blockIdx.z >> 2;
    int n0 = blockIdx.y*32, e0 = blockIdx.x*32;
    const float* in = that + (long long)b*N_*C_ + g*E_;
    float* out = kvsT + (long long)b*E_*FN_ + g*N_;
    int x = threadIdx.x, y = threadIdx.y;
    #pragma unroll
    for (int j = 0; j < 32; j += 8) {
        int n = n0 + y + j;
        if (n < N_) t[y+j][x] = in[(long long)n*C_ + e0 + x];
    }
    __syncthreads();
    #pragma unroll
    for (int j = 0; j < 32; j += 8) {
        int n = n0 + x;
        if (n < N_) out[(long long)(e0+y+j)*FN_ + n] = t[x][y+j];
    }
}

__global__ void merge0_kernel(const float* __restrict__ ctx, float* __restrict__ cm0) {
    int idx = blockIdx.x * blockDim.x + threadIdx.x;
    if (idx >= BN_*E_) return;
    int b = idx / NE_;
    int rem = idx % NE_;
    int n = rem / E_;
    int e = rem % E_;
    int h = e >> 6, d = e & 63;
    cm0[idx] = ctx[((long long)(b*H_ + h)*N_ + n)*HD_ + d];
}

// ---------------- templated tf32 mma.sync GEMM ----------------
// C = alpha*A@B^T (+bias)(+gelu)(+res). A:[M,K], B:[Ncol,K] row-major, inputs tf32-rounded.
__device__ __forceinline__ void epi_store(
    float* __restrict__ C, const float* __restrict__ bias, const float* __restrict__ res,
    int ldc, int row, int gc, int M, int act, int roundC, float alpha, float c0, float c1)
{
    if (row >= M) return;
    float2 v = make_float2(c0*alpha, c1*alpha);
    if (bias) { v.x += bias[gc]; v.y += bias[gc+1]; }
    if (act)  { v.x = gelu_f(v.x); v.y = gelu_f(v.y); }
    if (res)  { float2 rr = *(const float2*)(res + (long long)row*ldc + gc);
                v.x += rr.x; v.y += rr.y; }
    if (roundC) { v.x = tf32r(v.x); v.y = tf32r(v.y); }
    *(float2*)(C + (long long)row*ldc + gc) = v;
}

template<int TM, int TN, int WM, int WN>
__global__ void __launch_bounds__(256, 1) gemm_tc(
    int M, int Ncol, int K,
    const float* __restrict__ A, int lda,
    const float* __restrict__ B, int ldb,
    float* __restrict__ C, int ldc,
    const float* __restrict__ bias,
    const float* __restrict__ res,
    int act, int roundC, float alpha,
    int D0, int D1,
    long long sA0, long long sA1, long long sA2,
    long long sB0, long long sB1, long long sB2,
    long long sC0, long long sC1, long long sC2,
    long long sBias0, long long sBias1, long long sBias2,
    long long sR0, long long sR1, long long sR2)
{
    constexpr int WMS = TM / WM;            // warps along m
    constexpr int MI  = WM / 16;
    constexpr int NJ  = WN / 8;
    constexpr int ABUF = TM * 32;           // floats per buffer
    constexpr int BBUF = TN * 32;
    constexpr int ASLOT = (TM*2 + 255) / 256;
    constexpr int BSLOT = (TN*2 + 255) / 256;

    long long z = blockIdx.z;
    int z0 = (int)(z % D0); long long t = z / D0;
    int z1 = (int)(t % D1); int z2 = (int)(t / D1);
    A += z0*sA0 + z1*sA1 + z2*sA2;
    B += z0*sB0 + z1*sB1 + z2*sB2;
    C += z0*sC0 + z1*sC1 + z2*sC2;
    if (bias) bias += z0*sBias0 + z1*sBias1 + z2*sBias2;
    if (res)  res  += z0*sR0 + z1*sR1 + z2*sR2;

    extern __shared__ float sm[];
    float* As = sm;                 // 2 buffers
    float* Bs = sm + 2*ABUF;        // 2 buffers

    int tid = threadIdx.x;
    int lane = tid & 31;
    int wid = tid >> 5;
    int warp_m = wid % WMS;
    int warp_n = wid / WMS;
    int row0 = blockIdx.y * TM;
    int col0 = blockIdx.x * TN;

    float acc[MI][NJ][4];
    #pragma unroll
    for (int i = 0; i < MI; i++)
        #pragma unroll
        for (int j = 0; j < NJ; j++)
            #pragma unroll
            for (int q = 0; q < 4; q++) acc[i][j][q] = 0.f;

    // loader slot state
    const float* aPtr[ASLOT]; uint32_t aOff[ASLOT][4]; int aKh[ASLOT]; bool aV[ASLOT];
    const float* bPtr[BSLOT]; uint32_t bOff[BSLOT][4]; int bKh[BSLOT]; bool bV[BSLOT];
    #pragma unroll
    for (int i = 0; i < ASLOT; i++) {
        int sidx = tid + i*256;
        bool inA = sidx < TM*2;
        int r = inA ? (sidx >> 1) : 0;
        int kh = (sidx & 1) << 4;
        aKh[i] = kh;
        bool val = inA && (row0 + r) < M;
        aV[i] = val;
        aPtr[i] = A + (long long)(val ? row0 + r : 0) * lda;
        int sw = (r & 7) << 2;
        #pragma unroll
        for (int j = 0; j < 4; j++)
            aOff[i][j] = (uint32_t)((r*32 + ((kh + j*4) ^ sw)) << 2);
        if (!inA) aV[i] = false;
    }
    #pragma unroll
    for (int i = 0; i < BSLOT; i++) {
        int sidx = tid + i*256;
        bool inB = sidx < TN*2;
        int r = inB ? (sidx >> 1) : 0;
        int kh = (sidx & 1) << 4;
        bKh[i] = kh;
        bool val = inB && (col0 + r) < Ncol;
        bV[i] = val;
        bPtr[i] = B + (long long)(val ? col0 + r : 0) * ldb;
        int sw = (r & 7) << 2;
        #pragma unroll
        for (int j = 0; j < 4; j++)
            bOff[i][j] = (uint32_t)((r*32 + ((kh + j*4) ^ sw)) << 2);
        if (!inB) bV[i] = false;
    }

    uint32_t aSm = smem_u32(As);
    uint32_t bSm = smem_u32(Bs);
    int KT = (K + 31) >> 5;
    int lr = lane >> 2;
    int lc = lane & 3;

    // prologue: stage 0 -> buffer 0
    #pragma unroll
    for (int i = 0; i < ASLOT; i++) {
        bool sk = (ASLOT > 1) && (tid + i*256 >= TM*2);
        if (sk) continue;
        #pragma unroll
        for (int j = 0; j < 4; j++) {
            int gk = aKh[i] + j*4;
            int nb = (K - gk) * 4; nb = nb < 0 ? 0 : (nb > 16 ? 16 : nb);
            int ba = aV[i] ? nb : 0;
            cpa16(aSm + aOff[i][j], aPtr[i] + (ba ? gk : 0), ba);
        }
    }
    #pragma unroll
    for (int i = 0; i < BSLOT; i++) {
        bool sk = (tid + i*256 >= TN*2);
        if (sk) continue;
        #pragma unroll
        for (int j = 0; j < 4; j++) {
            int gk = bKh[i] + j*4;
            int nb = (K - gk) * 4; nb = nb < 0 ? 0 : (nb > 16 ? 16 : nb);
            int bb = bV[i] ? nb : 0;
            cpa16(bSm + bOff[i][j], bPtr[i] + (bb ? gk : 0), bb);
        }
    }
    CP_COMMIT();

    for (int kt = 0; kt < KT; kt++) {
        int p = kt & 1;
        __syncthreads();   // WAR on buffer 1-p
        if (kt + 1 < KT) {
            uint32_t aBo = (uint32_t)((1 - p) * ABUF * 4);
            uint32_t bBo = (uint32_t)((1 - p) * BBUF * 4);
            int k0 = (kt+1)*32;
            #pragma unroll
            for (int i = 0; i < ASLOT; i++) {
                bool sk = (ASLOT > 1) && (tid + i*256 >= TM*2);
                if (sk) continue;
                #pragma unroll
                for (int j = 0; j < 4; j++) {
                    int gk = k0 + aKh[i] + j*4;
                    int nb = (K - gk) * 4; nb = nb < 0 ? 0 : (nb > 16 ? 16 : nb);
                    int ba = aV[i] ? nb : 0;
                    cpa16(aSm + aBo + aOff[i][j], aPtr[i] + (ba ? gk : 0), ba);
                }
            }
            #pragma unroll
            for (int i = 0; i < BSLOT; i++) {
                bool sk = (tid + i*256 >= TN*2);
                if (sk) continue;
                #pragma unroll
                for (int j = 0; j < 4; j++) {
                    int gk = k0 + bKh[i] + j*4;
                    int nb = (K - gk) * 4; nb = nb < 0 ? 0 : (nb > 16 ? 16 : nb);
                    int bb = bV[i] ? nb : 0;
                    cpa16(bSm + bBo + bOff[i][j], bPtr[i] + (bb ? gk : 0), bb);
                }
            }
        }
        CP_COMMIT();
        CP_WAIT1();
        __syncthreads();   // RAW on buffer p

        const float* Ab = As + p*ABUF;
        const float* Bb = Bs + p*BBUF;
        #pragma unroll
        for (int ks = 0; ks < 4; ks++) {
            int kk = ks*8 + lc;
            uint32_t af[MI][4], bf[NJ][2];
            #pragma unroll
            for (int i = 0; i < MI; i++) {
                int m = warp_m*WM + i*16 + lr;
                int s = (m & 7) << 2;
                int c0 = kk ^ s, c1 = (kk + 4) ^ s;
                af[i][0] = __float_as_uint(Ab[m*32 + c0]);
                af[i][1] = __float_as_uint(Ab[(m+8)*32 + c0]);
                af[i][2] = __float_as_uint(Ab[m*32 + c1]);
                af[i][3] = __float_as_uint(Ab[(m+8)*32 + c1]);
            }
            #pragma unroll
            for (int j = 0; j < NJ; j++) {
                int n = warp_n*WN + j*8 + lr;
                int s = (n & 7) << 2;
                bf[j][0] = __float_as_uint(Bb[n*32 + (kk ^ s)]);
                bf[j][1] = __float_as_uint(Bb[n*32 + ((kk+4) ^ s)]);
            }
            #pragma unroll
            for (int i = 0; i < MI; i++)
                #pragma unroll
                for (int j = 0; j < NJ; j++)
                    mma_tf32(acc[i][j], af[i], bf[j]);
        }
    }

    #pragma unroll
    for (int i = 0; i < MI; i++) {
        int gr = row0 + warp_m*WM + i*16 + lr;
        #pragma unroll
        for (int j = 0; j < NJ; j++) {
            int gc = col0 + warp_n*WN + j*8 + lc*2;
            if (gc >= Ncol) continue;
            epi_store(C, bias, res, ldc, gr,   gc, M, act, roundC, alpha, acc[i][j][0], acc[i][j][1]);
            epi_store(C, bias, res, ldc, gr+8, gc, M, act, roundC, alpha, acc[i][j][2], acc[i][j][3]);
        }
    }
}

// ---------------- host ----------------
static float* symaddr(const void* sym) {
    void* p = nullptr;
    cudaGetSymbolAddress(&p, sym);
    return (float*)p;
}

#define G1 gemm_tc<128,128,64,32>
#define G2 gemm_tc<128,256,64,64>
#define G3 gemm_tc<128,64,32,32>
#define SM1 65536
#define SM2 98304
#define SM3 49152

extern "C" void kernel_launch(void* const* d_in, const int* in_sizes, int n_in,
                              void* d_out, int out_size) {
    const float* emb[4] = {(const float*)d_in[0], (const float*)d_in[1],
                           (const float*)d_in[2], (const float*)d_in[3]};
    const float* lag  = (const float*)d_in[4];
    const float* lab  = (const float*)d_in[5];
    const float* lcg  = (const float*)d_in[6];
    const float* lcb  = (const float*)d_in[7];
    const float* Wq   = (const float*)d_in[8];
    const float* Wk   = (const float*)d_in[9];
    const float* Wv   = (const float*)d_in[10];
    const float* Wo   = (const float*)d_in[11];
    const float* q_w  = (const float*)d_in[12];
    const float* k_w  = (const float*)d_in[13];
    const float* v_w  = (const float*)d_in[14];
    const float* outw = (const float*)d_in[15];
    const float* lfg  = (const float*)d_in[16];
    const float* lfb  = (const float*)d_in[17];
    const float* fc1w = (const float*)d_in[18];
    const float* fc1b = (const float*)d_in[19];
    const float* fc2w = (const float*)d_in[20];
    const float* fc2b = (const float*)d_in[21];
    float* out = (float*)d_out;

    cudaFuncSetAttribute(G1, cudaFuncAttributeMaxDynamicSharedMemorySize, SM1);
    cudaFuncSetAttribute(G2, cudaFuncAttributeMaxDynamicSharedMemorySize, SM2);
    cudaFuncSetAttribute(G3, cudaFuncAttributeMaxDynamicSharedMemorySize, SM3);

    float* cx   = symaddr(g_cx);   float* cxT  = symaddr(g_cxT);
    float* ec   = symaddr(g_ec);
    float* qc   = symaddr(g_qc);   float* kc   = symaddr(g_kc);
    float* vc   = symaddr(g_vc);   float* vcT  = symaddr(g_vcT);
    float* sch  = symaddr(g_sch);  float* tbuf = symaddr(g_t);
    float* that = symaddr(g_that); float* kvsT = symaddr(g_kvsT);
    float* KV   = symaddr(g_KV);   float* VT   = symaddr(g_VT);
    float* Qb   = symaddr(g_Q);    float* attn = symaddr(g_attn);
    float* rstdp= symaddr(g_rstd);
    float* ctx  = symaddr(g_ctx);  float* cm0  = symaddr(g_cm0);
    float* hbuf = symaddr(g_h);    float* xln  = symaddr(g_xln);
    float* x1   = symaddr(g_x1);
    float* qwT  = symaddr(g_qwT);  float* kvwT = symaddr(g_kvwT);
    float* WqT  = symaddr(g_WqT);  float* WkT  = symaddr(g_WkT);
    float* WvT  = symaddr(g_WvT);  float* WoT  = symaddr(g_WoT);
    float* outwT= symaddr(g_outwT);
    float* fc1wT= symaddr(g_fc1wT);float* fc2wT= symaddr(g_fc2wT);

    const long long Z = 0;
    dim3 tb(32, 8);

    // 1. fused LayerNorms
    ln_fused_kernel<<<BN_, 256>>>(emb[0], emb[1], emb[2], emb[3], lag, lab, lcg, lcb, cx, ec);

    // 2. weight transposes (rounded)
    transpose_tiled<<<dim3(64, 64, 1), tb>>>(Wq, WqT, C_, C_, 1);
    transpose_tiled<<<dim3(64, 64, 1), tb>>>(Wk, WkT, C_, C_, 1);
    transpose_tiled<<<dim3(64, 64, 1), tb>>>(Wv, WvT, C_, C_, 1);
    transpose_tiled<<<dim3(64, 64, 1), tb>>>(Wo, WoT, C_, C_, 1);
    transpose_tiled<<<dim3(7, 7, 4),   tb>>>(q_w, qwT, N_, N_, 1);
    transpose_tiled<<<dim3(25, 25, 1), tb>>>(k_w, kvwT, FN_, FN_, 1);
    transpose_tiled<<<dim3(25, 25, 1), tb>>>(v_w, kvwT + (long long)FN_*FN_, FN_, FN_, 1);
    transpose_tiled<<<dim3(16, 16, 4), tb>>>(outw, outwT, E_, E_, 1);
    transpose_tiled<<<dim3(64, 16, 4), tb>>>(fc1w, fc1wT, E_, 2048, 1);
    transpose_tiled<<<dim3(16, 64, 4), tb>>>(fc2w, fc2wT, 2048, E_, 1);
    transpose_tiled<<<dim3(16, 7, 64), tb>>>(cx, cxT, N_, E_, 0);

    // 3. channel projections: [3136,2048,2048]
    {
        dim3 g(8, 25, 1);
        G2<<<g,256,SM2>>>(BN_, C_, C_, ec, C_, WqT, C_, qc, C_, nullptr, nullptr, 0, 1, 1.f,
                           1,1, Z,Z,Z, Z,Z,Z, Z,Z,Z, Z,Z,Z, Z,Z,Z);
        G2<<<g,256,SM2>>>(BN_, C_, C_, ec, C_, WkT, C_, kc, C_, nullptr, nullptr, 0, 1, 1.f,
                           1,1, Z,Z,Z, Z,Z,Z, Z,Z,Z, Z,Z,Z, Z,Z,Z);
        G2<<<g,256,SM2>>>(BN_, C_, C_, ec, C_, WvT, C_, vc, C_, nullptr, nullptr, 0, 1, 1.f,
                           1,1, Z,Z,Z, Z,Z,Z, Z,Z,Z, Z,Z,Z, Z,Z,Z);
    }
    transpose_tiled<<<dim3(64, 7, 16), tb>>>(vc, vcT, N_, C_, 0);

    // 4. channel scores per (h,b): [196,196,256]
    {
        dim3 g(2, 2, B_*H_);
        G1<<<g,256,SM1>>>(N_, N_, HDC_, qc, C_, kc, C_, sch, N_, nullptr, nullptr, 0, 0, 0.0625f,
                           H_, B_,
                           256LL, (long long)N_*C_, Z,
                           256LL, (long long)N_*C_, Z,
                           (long long)SCHZ_, (long long)H_*SCHZ_, Z,
                           Z,Z,Z, Z,Z,Z);
    }
    // 5. channel softmax
    softmax_fix<1,false><<<B_*H_*N_, 256>>>(sch, N_, 1, nullptr, 1.f);

    // 6. T = s @ v per (h,b): [196,256,196]
    {
        dim3 g(1, 2, B_*H_);
        G2<<<g,256,SM2>>>(N_, HDC_, N_, sch, N_, vcT, N_, tbuf, C_, nullptr, nullptr, 0, 1, 1.f,
                           H_, B_,
                           (long long)SCHZ_, (long long)H_*SCHZ_, Z,
                           (long long)(256*N_), (long long)C_*N_, Z,
                           256LL, (long long)N_*C_, Z,
                           Z,Z,Z, Z,Z,Z);
    }
    // 7. T_hat = T @ Wo
    {
        dim3 g(8, 25, 1);
        G2<<<g,256,SM2>>>(BN_, C_, C_, tbuf, C_, WoT, C_, that, C_, nullptr, nullptr, 0, 1, 1.f,
                           1,1, Z,Z,Z, Z,Z,Z, Z,Z,Z, Z,Z,Z, Z,Z,Z);
    }
    // 8. fused KV_S reshape + transpose
    kvsT_kernel<<<dim3(16, 7, 64), tb>>>(that, kvsT);

    // 9. K/V token-mix merged: [784,512,784] per (which,b)
    {
        dim3 g(2, 7, 2*B_);
        G2<<<g,256,SM2>>>(FN_, E_, FN_, kvwT, FN_, kvsT, FN_, KV, E_, nullptr, nullptr, 0, 1, 1.f,
                           2, B_,
                           (long long)FN_*FN_, Z, Z,
                           Z, (long long)E_*FN_, Z,
                           (long long)B_*FNE_, (long long)FNE_, Z,
                           Z,Z,Z, Z,Z,Z);
    }
    transpose_tiled<<<dim3(16, 25, 16), tb>>>(KV + (long long)B_*FNE_, VT, FN_, E_, 0);

    // 10. Q token-mix per (b,g): [196,512,196]
    {
        dim3 g(2, 2, 4*B_);
        G2<<<g,256,SM2>>>(N_, E_, N_, qwT, N_, cxT, N_, Qb, E_, nullptr, nullptr, 0, 1, 1.f,
                           B_, 4,
                           Z, (long long)SCHZ_, Z,
                           (long long)(E_*N_), (long long)B_*E_*N_, Z,
                           (long long)NE_, (long long)BNE_, Z,
                           Z,Z,Z, Z,Z,Z);
    }
    // 11. spatial logits per (h,b,g): [196,784,64]
    {
        dim3 g(7, 2, 512);
        G1<<<g,256,SM1>>>(N_, FN_, HD_, Qb, E_, KV, E_, attn, FN_, nullptr, nullptr, 0, 0, 1.f,
                           H_, B_,
                           64LL, (long long)NE_,  (long long)BNE_,
                           64LL, (long long)FNE_, Z,
                           (long long)ATTZ_, (long long)H_*ATTZ_, (long long)B_*H_*ATTZ_,
                           Z,Z,Z, Z,Z,Z);
    }
    // 12-13. instance-norm rstd + softmax
    inorm_stats_kernel<<<512, 512>>>(attn, rstdp);
    softmax_fix<4,true><<<512*N_, 256>>>(attn, FN_, N_, rstdp, 1.f);

    // 14. ctx = p @ Vh per (h,b,g): [196,64,784]
    {
        dim3 g(1, 2, 512);
        G3<<<g,256,SM3>>>(N_, HD_, FN_, attn, FN_, VT, FN_, ctx, HD_, nullptr, nullptr, 0, 1, 1.f,
                           H_, B_,
                           (long long)ATTZ_, (long long)H_*ATTZ_, (long long)B_*H_*ATTZ_,
                           (long long)(HD_*FN_), (long long)E_*FN_, Z,
                           (long long)(N_*HD_), (long long)(H_*N_*HD_), (long long)(B_*H_*N_*HD_),
                           Z,Z,Z, Z,Z,Z);
    }
    // 15. branch-0 head permute
    merge0_kernel<<<(BN_*E_ + 255)/256, 256>>>(ctx, cm0);

    // 16. out projection + residual-1 (exact fp32)
    {
        dim3 g(2, 25, 1);
        for (int gg = 0; gg < 4; gg++) {
            const float* Ag = (gg == 0) ? cm0 : (ctx + (long long)gg * BNE_);
            G2<<<g,256,SM2>>>(BN_, E_, E_, Ag, E_, outwT + (long long)gg*E_*E_, E_,
                               hbuf + (long long)gg*BNE_, E_,
                               nullptr, emb[gg], 0, 0, 1.f,
                               1,1, Z,Z,Z, Z,Z,Z, Z,Z,Z, Z,Z,Z, Z,Z,Z);
        }
    }
    // 17. FFN LayerNorm
    ln_rows_kernel<<<4*BN_, 256>>>(hbuf, lfg, lfb, xln, BN_);

    // 18. fc1 + bias + GELU per g: [3136,2048,512]
    {
        dim3 g(8, 25, 4);
        G2<<<g,256,SM2>>>(BN_, 4*E_, E_, xln, E_, fc1wT, E_, x1, 4*E_,
                           fc1b, nullptr, 1, 1, 1.f,
                           4, 1,
                           (long long)BNE_, Z, Z,
                           (long long)(2048*E_), Z, Z,
                           (long long)BN_*4*E_, Z, Z,
                           (long long)(4*E_), Z, Z,
                           Z,Z,Z);
    }
    // 19. fc2 + bias + residual-2 -> out (exact fp32)
    {
        dim3 g(2, 25, 4);
        G2<<<g,256,SM2>>>(BN_, E_, 4*E_, x1, 4*E_, fc2wT, 4*E_, out, E_,
                           fc2b, hbuf, 0, 0, 1.f,
                           4, 1,
                           (long long)BN_*4*E_, Z, Z,
                           (long long)(E_*2048), Z, Z,
                           (long long)BNE_, Z, Z,
                           (long long)E_, Z, Z,
                           (long long)BNE_, Z, Z);
    }
}

// round 7
// speedup vs baseline: 6.3165x; 1.5897x over previous
#include <cuda_runtime.h>
#include <cuda_fp16.h>
#include <cstdint>
#include <math.h>

#define B_     16
#define N_     196
#define E_     512
#define H_     8
#define HD_    64
#define C_     2048
#define HDC_   256
#define FN_    784
#define BN_    3136
#define NE_    100352
#define FNE_   401408
#define BNE_   1605632
#define SCHZ_  38416
#define ATTZ_  153664
#define LP_    200            // padded lda for 196-wide K rows

// ---------------- scratch ----------------
__device__ __align__(128) __half h_cx  [4*BN_*E_];
__device__ __align__(128) __half h_cxT [4*B_*E_*LP_];
__device__ __align__(128) __half h_ec  [BN_*C_];
__device__ __align__(128) __half h_qc  [BN_*C_];
__device__ __align__(128) __half h_kc  [BN_*C_];
__device__ __align__(128) __half h_vc  [BN_*C_];
__device__ __align__(128) __half h_vcT [B_*C_*LP_];
__device__ __align__(128) float  g_sch [B_*H_*N_*N_];      // channel logits fp32
__device__ __align__(128) __half h_sch [B_*H_*N_*LP_];     // channel probs
__device__ __align__(128) __half h_t   [BN_*C_];
__device__ __align__(128) __half h_that[BN_*C_];
__device__ __align__(128) __half h_kvsT[B_*E_*FN_];
__device__ __align__(128) __half h_KV  [2*B_*FN_*E_];      // K then V
__device__ __align__(128) __half h_VT  [B_*E_*FN_];
__device__ __align__(128) __half h_Q   [4*BN_*E_];
__device__ __align__(128) float  g_attn[512u*196*784];     // spatial logits fp32
__device__ __align__(128) __half h_attn[512u*196*784];     // spatial probs
__device__ __align__(128) float  g_rstd[512];
__device__ __align__(128) __half h_ctx [4*B_*H_*N_*HD_];
__device__ __align__(128) __half h_cm0 [BN_*E_];
__device__ __align__(128) float  g_h   [4*BN_*E_];
__device__ __align__(128) __half h_xln [4*BN_*E_];
__device__ __align__(128) __half h_x1  [4*BN_*2048];
__device__ __align__(128) __half h_qwT [4*N_*LP_];
__device__ __align__(128) __half h_kvwT[2*FN_*FN_];
__device__ __align__(128) __half h_WqT [C_*C_];
__device__ __align__(128) __half h_WkT [C_*C_];
__device__ __align__(128) __half h_WvT [C_*C_];
__device__ __align__(128) __half h_WoT [C_*C_];
__device__ __align__(128) __half h_outwT[4*E_*E_];
__device__ __align__(128) __half h_fc1wT[4*2048*E_];
__device__ __align__(128) __half h_fc2wT[4*E_*2048];

// ---------------- helpers ----------------
__device__ __forceinline__ uint32_t smem_u32(const void* p) {
    uint32_t a;
    asm("{ .reg .u64 t; cvta.to.shared.u64 t, %1; cvt.u32.u64 %0, t; }" : "=r"(a) : "l"(p));
    return a;
}
__device__ __forceinline__ void mma_f16(float* d, const uint32_t* a, const uint32_t* b) {
    asm volatile(
        "mma.sync.aligned.m16n8k16.row.col.f32.f16.f16.f32 "
        "{%0,%1,%2,%3}, {%4,%5,%6,%7}, {%8,%9}, {%0,%1,%2,%3};"
        : "+f"(d[0]), "+f"(d[1]), "+f"(d[2]), "+f"(d[3])
        : "r"(a[0]), "r"(a[1]), "r"(a[2]), "r"(a[3]), "r"(b[0]), "r"(b[1]));
}
__device__ __forceinline__ float gelu_f(float v) {
    return 0.5f * v * (1.f + erff(v * 0.70710678118654752f));
}
__device__ __forceinline__ void cpa16(uint32_t dst, const __half* src, int bytes) {
    asm volatile("cp.async.ca.shared.global [%0], [%1], 16, %2;"
                 :: "r"(dst), "l"(src), "r"(bytes) : "memory");
}
#define CP_COMMIT() asm volatile("cp.async.commit_group;" ::: "memory")
#define CP_WAIT1()  asm volatile("cp.async.wait_group 1;" ::: "memory")

// ---------------- reductions ----------------
__device__ __forceinline__ float block_sum(float v, float* sh) {
    int tid = threadIdx.x;
    #pragma unroll
    for (int o = 16; o > 0; o >>= 1) v += __shfl_down_sync(0xffffffffu, v, o);
    if ((tid & 31) == 0) sh[tid >> 5] = v;
    __syncthreads();
    if (tid < 32) {
        float t = (tid < (int)(blockDim.x >> 5)) ? sh[tid] : 0.f;
        #pragma unroll
        for (int o = 16; o > 0; o >>= 1) t += __shfl_down_sync(0xffffffffu, t, o);
        if (tid == 0) sh[0] = t;
    }
    __syncthreads();
    float r = sh[0];
    __syncthreads();
    return r;
}
__device__ __forceinline__ float block_max(float v, float* sh) {
    int tid = threadIdx.x;
    #pragma unroll
    for (int o = 16; o > 0; o >>= 1) v = fmaxf(v, __shfl_down_sync(0xffffffffu, v, o));
    if ((tid & 31) == 0) sh[tid >> 5] = v;
    __syncthreads();
    if (tid < 32) {
        float t = (tid < (int)(blockDim.x >> 5)) ? sh[tid] : -INFINITY;
        #pragma unroll
        for (int o = 16; o > 0; o >>= 1) t = fmaxf(t, __shfl_down_sync(0xffffffffu, t, o));
        if (tid == 0) sh[0] = t;
    }
    __syncthreads();
    float r = sh[0];
    __syncthreads();
    return r;
}

// ---------------- LN (half outputs) ----------------
__global__ void __launch_bounds__(256) ln_fused_kernel(
    const float* __restrict__ e1, const float* __restrict__ e2,
    const float* __restrict__ e3, const float* __restrict__ e4,
    const float* __restrict__ lag, const float* __restrict__ lab,
    const float* __restrict__ lcg, const float* __restrict__ lcb,
    __half* __restrict__ cx, __half* __restrict__ ec)
{
    __shared__ float sh[32];
    int token = blockIdx.x;
    int tid = threadIdx.x;
    const float* es[4] = {e1, e2, e3, e4};
    float x[4][2], mg[4], rg[4];
    float stot = 0.f, sstot = 0.f;
    #pragma unroll
    for (int g = 0; g < 4; g++) {
        const float* p = es[g] + (long long)token * E_;
        x[g][0] = p[tid]; x[g][1] = p[tid + 256];
        float s  = block_sum(x[g][0] + x[g][1], sh);
        float ss = block_sum(x[g][0]*x[g][0] + x[g][1]*x[g][1], sh);
        float m = s * (1.f/512.f);
        float v = ss * (1.f/512.f) - m*m;
        mg[g] = m; rg[g] = rsqrtf(v + 1e-6f);
        stot += s; sstot += ss;
    }
    float m = stot * (1.f/2048.f);
    float r = rsqrtf(sstot * (1.f/2048.f) - m*m + 1e-6f);
    #pragma unroll
    for (int g = 0; g < 4; g++) {
        #pragma unroll
        for (int j = 0; j < 2; j++) {
            int e = tid + j*256;
            float xv = x[g][j];
            cx[((long long)g*BN_ + token)*E_ + e] =
                __float2half_rn((xv - mg[g]) * rg[g] * lag[g*E_+e] + lab[g*E_+e]);
            ec[(long long)token*C_ + g*E_ + e] =
                __float2half_rn((xv - m) * r * lcg[g*E_+e] + lcb[g*E_+e]);
        }
    }
}

__global__ void __launch_bounds__(256) ln_rows_kernel(
    const float* __restrict__ X, const float* __restrict__ gamma,
    const float* __restrict__ beta, __half* __restrict__ Y, int rowsPerG)
{
    __shared__ float sh[32];
    long long row = blockIdx.x;
    int tid = threadIdx.x;
    int g = (int)(row / rowsPerG);
    const float* p = X + row * E_;
    float x0 = p[tid], x1 = p[tid+256];
    float s  = block_sum(x0 + x1, sh);
    float ss = block_sum(x0*x0 + x1*x1, sh);
    float m = s * (1.f/512.f);
    float r = rsqrtf(ss * (1.f/512.f) - m*m + 1e-6f);
    __half* q = Y + row * E_;
    q[tid]     = __float2half_rn((x0 - m) * r * gamma[g*E_+tid]     + beta[g*E_+tid]);
    q[tid+256] = __float2half_rn((x1 - m) * r * gamma[g*E_+tid+256] + beta[g*E_+tid+256]);
}

// ---------------- instance-norm rstd ----------------
__global__ void __launch_bounds__(512) inorm_stats_kernel(
    const float* __restrict__ attn, float* __restrict__ rstd)
{
    __shared__ float sh[32];
    int z = blockIdx.x;
    const float* p = attn + (long long)z * ATTZ_;
    float s = 0.f, ss = 0.f;
    for (int i = threadIdx.x; i < ATTZ_; i += 512) {
        float v = p[i]; s += v; ss += v*v;
    }
    s  = block_sum(s, sh);
    ss = block_sum(ss, sh);
    if (threadIdx.x == 0) {
        float m = s * (1.f/(float)ATTZ_);
        rstd[z] = rsqrtf(ss * (1.f/(float)ATTZ_) - m*m + 1e-5f);
    }
}

// ---------------- softmax: fp32 logits in, half probs out ----------------
template<int NIT, bool PERZ>
__global__ void __launch_bounds__(256) softmax_fix(
    const float* __restrict__ S, __half* __restrict__ O,
    int cols, int ldo, int rowsPerZ,
    const float* __restrict__ rstd, float scale)
{
    __shared__ float sh[32];
    long long row = blockIdx.x;
    const float* p = S + row * cols;
    __half* q = O + row * ldo;
    float sc = PERZ ? rstd[(int)(row / rowsPerZ)] : scale;
    int tid = threadIdx.x;
    float vals[NIT];
    float mx = -INFINITY;
    #pragma unroll
    for (int it = 0; it < NIT; it++) {
        int i = tid + it*256;
        float t = (i < cols) ? p[i]*sc : -INFINITY;
        vals[it] = t;
        mx = fmaxf(mx, t);
    }
    mx = block_max(mx, sh);
    float s = 0.f;
    #pragma unroll
    for (int it = 0; it < NIT; it++) {
        float e = expf(vals[it] - mx);
        vals[it] = e;
        s += e;
    }
    s = block_sum(s, sh);
    float inv = 1.f / s;
    #pragma unroll
    for (int it = 0; it < NIT; it++) {
        int i = tid + it*256;
        if (i < cols) q[i] = __float2half_rn(vals[it] * inv);
    }
}

// ---------------- tiled transpose (typed, padded out) ----------------
template<typename TI, typename TO>
__global__ void transpose_t(const TI* __restrict__ in, TO* __restrict__ out,
                            int R, int Cc, int ldo, long long zi, long long zo)
{
    __shared__ float t[32][33];
    const TI* ip = in + (long long)blockIdx.z * zi;
    TO* op = out + (long long)blockIdx.z * zo;
    int c0 = blockIdx.x*32, r0 = blockIdx.y*32;
    int x = threadIdx.x, y = threadIdx.y;
    #pragma unroll
    for (int j = 0; j < 32; j += 8) {
        int r = r0 + y + j, c = c0 + x;
        if (r < R && c < Cc) t[y+j][x] = (float)ip[(long long)r*Cc + c];
    }
    __syncthreads();
    #pragma unroll
    for (int j = 0; j < 32; j += 8) {
        int c = c0 + y + j, r = r0 + x;
        if (r < R && c < Cc) op[(long long)c*ldo + r] = (TO)t[x][y+j];
    }
}

// kvsT[b][e][g*196+n] = that[b][n][g*512+e]  (half)
__global__ void kvsT_kernel(const __half* __restrict__ that, __half* __restrict__ kvsT)
{
    __shared__ __half t[32][34];
    int g = blockIdx.z & 3, b = blockIdx.z >> 2;
    int n0 = blockIdx.y*32, e0 = blockIdx.x*32;
    const __half* in = that + (long long)b*N_*C_ + g*E_;
    __half* out = kvsT + (long long)b*E_*FN_ + g*N_;
    int x = threadIdx.x, y = threadIdx.y;
    #pragma unroll
    for (int j = 0; j < 32; j += 8) {
        int n = n0 + y + j;
        if (n < N_) t[y+j][x] = in[(long long)n*C_ + e0 + x];
    }
    __syncthreads();
    #pragma unroll
    for (int j = 0; j < 32; j += 8) {
        int n = n0 + x;
        if (n < N_) out[(long long)(e0+y+j)*FN_ + n] = t[x][y+j];
    }
}

__global__ void merge0_kernel(const __half* __restrict__ ctx, __half* __restrict__ cm0) {
    int idx = blockIdx.x * blockDim.x + threadIdx.x;
    if (idx >= BN_*E_) return;
    int b = idx / NE_;
    int rem = idx % NE_;
    int n = rem / E_;
    int e = rem % E_;
    int h = e >> 6, d = e & 63;
    cm0[idx] = ctx[((long long)(b*H_ + h)*N_ + n)*HD_ + d];
}

// ---------------- fp16 mma.sync GEMM, cp.async double-buffered ----------------
// C = alpha*A@B^T (+bias)(+gelu)(+res). A:[M,K], B:[Ncol,K] half row-major.
// K-tile 64 halves = 128B/row. 256 thr.
__device__ __forceinline__ void epi_store(
    void* __restrict__ Cv, const float* __restrict__ bias, const float* __restrict__ res,
    int ldc, int row, int gc, int M, int act, int outHalf, float alpha, float c0, float c1)
{
    if (row >= M) return;
    float2 v = make_float2(c0*alpha, c1*alpha);
    if (bias) { v.x += bias[gc]; v.y += bias[gc+1]; }
    if (act)  { v.x = gelu_f(v.x); v.y = gelu_f(v.y); }
    if (res)  { float2 rr = *(const float2*)(res + (long long)row*ldc + gc);
                v.x += rr.x; v.y += rr.y; }
    if (outHalf) {
        *(__half2*)((__half*)Cv + (long long)row*ldc + gc) = __floats2half2_rn(v.x, v.y);
    } else {
        *(float2*)((float*)Cv + (long long)row*ldc + gc) = v;
    }
}

template<int TM, int TN, int WM, int WN>
__global__ void __launch_bounds__(256, 1) gemm_h(
    int M, int Ncol, int K,
    const __half* __restrict__ A, int lda,
    const __half* __restrict__ B, int ldb,
    void* __restrict__ Cv, int ldc,
    const float* __restrict__ bias,
    const float* __restrict__ res,
    int act, int outHalf, float alpha,
    int D0, int D1,
    long long sA0, long long sA1, long long sA2,
    long long sB0, long long sB1, long long sB2,
    long long sC0, long long sC1, long long sC2,
    long long sBias0, long long sR0)
{
    constexpr int WMS = TM / WM;
    constexpr int MI  = WM / 16;
    constexpr int NJ  = WN / 8;
    constexpr int ABUFW = TM * 32;   // words per buffer (row = 32 words = 64 halves)
    constexpr int BBUFW = TN * 32;
    constexpr int ASLOT = (TM*2 + 255) / 256;
    constexpr int BSLOT = (TN*2 + 255) / 256;

    long long z = blockIdx.z;
    int z0 = (int)(z % D0); long long t = z / D0;
    int z1 = (int)(t % D1); int z2 = (int)(t / D1);
    A += z0*sA0 + z1*sA1 + z2*sA2;
    B += z0*sB0 + z1*sB1 + z2*sB2;
    long long coff = z0*sC0 + z1*sC1 + z2*sC2;
    Cv = outHalf ? (void*)((__half*)Cv + coff) : (void*)((float*)Cv + coff);
    if (bias) bias += z0*sBias0;
    if (res)  res  += z0*sR0;

    extern __shared__ uint32_t smw[];
    uint32_t* As = smw;
    uint32_t* Bs = smw + 2*ABUFW;

    int tid = threadIdx.x;
    int lane = tid & 31;
    int wid = tid >> 5;
    int warp_m = wid % WMS;
    int warp_n = wid / WMS;
    int row0 = blockIdx.y * TM;
    int col0 = blockIdx.x * TN;

    float acc[MI][NJ][4];
    #pragma unroll
    for (int i = 0; i < MI; i++)
        #pragma unroll
        for (int j = 0; j < NJ; j++)
            #pragma unroll
            for (int q = 0; q < 4; q++) acc[i][j][q] = 0.f;

    const __half* aPtr[ASLOT]; uint32_t aOff[ASLOT][4]; int aKh[ASLOT]; bool aV[ASLOT];
    const __half* bPtr[BSLOT]; uint32_t bOff[BSLOT][4]; int bKh[BSLOT]; bool bV[BSLOT];
    #pragma unroll
    for (int i = 0; i < ASLOT; i++) {
        int sidx = tid + i*256;
        bool inA = sidx < TM*2;
        int r = inA ? (sidx >> 1) : 0;
        int khw = (sidx & 1) * 16;          // word base within row
        aKh[i] = (sidx & 1) * 32;           // half base within row
        bool val = inA && (row0 + r) < M;
        aV[i] = val;
        aPtr[i] = A + (long long)(val ? row0 + r : 0) * lda;
        int sw = (r & 7) << 2;
        #pragma unroll
        for (int j = 0; j < 4; j++)
            aOff[i][j] = (uint32_t)((r*32 + ((khw + j*4) ^ sw)) << 2);
    }
    #pragma unroll
    for (int i = 0; i < BSLOT; i++) {
        int sidx = tid + i*256;
        bool inB = sidx < TN*2;
        int r = inB ? (sidx >> 1) : 0;
        int khw = (sidx & 1) * 16;
        bKh[i] = (sidx & 1) * 32;
        bool val = inB && (col0 + r) < Ncol;
        bV[i] = val;
        bPtr[i] = B + (long long)(val ? col0 + r : 0) * ldb;
        int sw = (r & 7) << 2;
        #pragma unroll
        for (int j = 0; j < 4; j++)
            bOff[i][j] = (uint32_t)((r*32 + ((khw + j*4) ^ sw)) << 2);
    }

    uint32_t aSm = smem_u32(As);
    uint32_t bSm = smem_u32(Bs);
    int KT = (K + 63) >> 6;
    int lr = lane >> 2;
    int lc = lane & 3;

    // prologue -> buffer 0
    #pragma unroll
    for (int i = 0; i < ASLOT; i++) {
        if ((ASLOT > 1) && (tid + i*256 >= TM*2)) continue;
        #pragma unroll
        for (int j = 0; j < 4; j++) {
            int gk = aKh[i] + j*8;
            int nb = (K - gk) * 2; nb = nb < 0 ? 0 : (nb > 16 ? 16 : nb);
            int ba = aV[i] ? nb : 0;
            cpa16(aSm + aOff[i][j], aPtr[i] + (ba ? gk : 0), ba);
        }
    }
    #pragma unroll
    for (int i = 0; i < BSLOT; i++) {
        if (tid + i*256 >= TN*2) continue;
        #pragma unroll
        for (int j = 0; j < 4; j++) {
            int gk = bKh[i] + j*8;
            int nb = (K - gk) * 2; nb = nb < 0 ? 0 : (nb > 16 ? 16 : nb);
            int bb = bV[i] ? nb : 0;
            cpa16(bSm + bOff[i][j], bPtr[i] + (bb ? gk : 0), bb);
        }
    }
    CP_COMMIT();

    for (int kt = 0; kt < KT; kt++) {
        int p = kt & 1;
        __syncthreads();
        if (kt + 1 < KT) {
            uint32_t aBo = (uint32_t)((1 - p) * ABUFW * 4);
            uint32_t bBo = (uint32_t)((1 - p) * BBUFW * 4);
            int k0 = (kt+1)*64;
            #pragma unroll
            for (int i = 0; i < ASLOT; i++) {
                if ((ASLOT > 1) && (tid + i*256 >= TM*2)) continue;
                #pragma unroll
                for (int j = 0; j < 4; j++) {
                    int gk = k0 + aKh[i] + j*8;
                    int nb = (K - gk) * 2; nb = nb < 0 ? 0 : (nb > 16 ? 16 : nb);
                    int ba = aV[i] ? nb : 0;
                    cpa16(aSm + aBo + aOff[i][j], aPtr[i] + (ba ? gk : 0), ba);
                }
            }
            #pragma unroll
            for (int i = 0; i < BSLOT; i++) {
                if (tid + i*256 >= TN*2) continue;
                #pragma unroll
                for (int j = 0; j < 4; j++) {
                    int gk = k0 + bKh[i] + j*8;
                    int nb = (K - gk) * 2; nb = nb < 0 ? 0 : (nb > 16 ? 16 : nb);
                    int bb = bV[i] ? nb : 0;
                    cpa16(bSm + bBo + bOff[i][j], bPtr[i] + (bb ? gk : 0), bb);
                }
            }
        }
        CP_COMMIT();
        CP_WAIT1();
        __syncthreads();

        const uint32_t* Ab = As + p*ABUFW;
        const uint32_t* Bb = Bs + p*BBUFW;
        #pragma unroll
        for (int ks = 0; ks < 4; ks++) {
            int w0 = ks*8 + lc;
            int w1 = w0 + 4;
            uint32_t af[MI][4], bf[NJ][2];
            #pragma unroll
            for (int i = 0; i < MI; i++) {
                int m = warp_m*WM + i*16 + lr;
                int s = (m & 7) << 2;
                af[i][0] = Ab[m*32 + (w0 ^ s)];
                af[i][1] = Ab[(m+8)*32 + (w0 ^ s)];
                af[i][2] = Ab[m*32 + (w1 ^ s)];
                af[i][3] = Ab[(m+8)*32 + (w1 ^ s)];
            }
            #pragma unroll
            for (int j = 0; j < NJ; j++) {
                int n = warp_n*WN + j*8 + lr;
                int s = (n & 7) << 2;
                bf[j][0] = Bb[n*32 + (w0 ^ s)];
                bf[j][1] = Bb[n*32 + (w1 ^ s)];
            }
            #pragma unroll
            for (int i = 0; i < MI; i++)
                #pragma unroll
                for (int j = 0; j < NJ; j++)
                    mma_f16(acc[i][j], af[i], bf[j]);
        }
    }

    #pragma unroll
    for (int i = 0; i < MI; i++) {
        int gr = row0 + warp_m*WM + i*16 + lr;
        #pragma unroll
        for (int j = 0; j < NJ; j++) {
            int gc = col0 + warp_n*WN + j*8 + lc*2;
            if (gc >= Ncol) continue;
            epi_store(Cv, bias, res, ldc, gr,   gc, M, act, outHalf, alpha, acc[i][j][0], acc[i][j][1]);
            epi_store(Cv, bias, res, ldc, gr+8, gc, M, act, outHalf, alpha, acc[i][j][2], acc[i][j][3]);
        }
    }
}

// ---------------- host ----------------
static void* symaddr(const void* sym) {
    void* p = nullptr;
    cudaGetSymbolAddress(&p, sym);
    return p;
}

#define G1 gemm_h<128,128,64,32>
#define G2 gemm_h<128,256,64,64>
#define G3 gemm_h<128,64,32,32>
#define SM1 65536
#define SM2 98304
#define SM3 49152

extern "C" void kernel_launch(void* const* d_in, const int* in_sizes, int n_in,
                              void* d_out, int out_size) {
    const float* emb[4] = {(const float*)d_in[0], (const float*)d_in[1],
                           (const float*)d_in[2], (const float*)d_in[3]};
    const float* lag  = (const float*)d_in[4];
    const float* lab  = (const float*)d_in[5];
    const float* lcg  = (const float*)d_in[6];
    const float* lcb  = (const float*)d_in[7];
    const float* Wq   = (const float*)d_in[8];
    const float* Wk   = (const float*)d_in[9];
    const float* Wv   = (const float*)d_in[10];
    const float* Wo   = (const float*)d_in[11];
    const float* q_w  = (const float*)d_in[12];
    const float* k_w  = (const float*)d_in[13];
    const float* v_w  = (const float*)d_in[14];
    const float* outw = (const float*)d_in[15];
    const float* lfg  = (const float*)d_in[16];
    const float* lfb  = (const float*)d_in[17];
    const float* fc1w = (const float*)d_in[18];
    const float* fc1b = (const float*)d_in[19];
    const float* fc2w = (const float*)d_in[20];
    const float* fc2b = (const float*)d_in[21];
    float* out = (float*)d_out;

    cudaFuncSetAttribute(G1, cudaFuncAttributeMaxDynamicSharedMemorySize, SM1);
    cudaFuncSetAttribute(G2, cudaFuncAttributeMaxDynamicSharedMemorySize, SM2);
    cudaFuncSetAttribute(G3, cudaFuncAttributeMaxDynamicSharedMemorySize, SM3);

    __half* cx   = (__half*)symaddr(h_cx);   __half* cxT = (__half*)symaddr(h_cxT);
    __half* ec   = (__half*)symaddr(h_ec);
    __half* qc   = (__half*)symaddr(h_qc);   __half* kc  = (__half*)symaddr(h_kc);
    __half* vc   = (__half*)symaddr(h_vc);   __half* vcT = (__half*)symaddr(h_vcT);
    float*  sch  = (float*)symaddr(g_sch);   __half* schh= (__half*)symaddr(h_sch);
    __half* tbuf = (__half*)symaddr(h_t);    __half* that= (__half*)symaddr(h_that);
    __half* kvsT = (__half*)symaddr(h_kvsT);
    __half* KV   = (__half*)symaddr(h_KV);   __half* VT  = (__half*)symaddr(h_VT);
    __half* Qb   = (__half*)symaddr(h_Q);
    float*  attn = (float*)symaddr(g_attn);  __half* attnh=(__half*)symaddr(h_attn);
    float*  rstdp= (float*)symaddr(g_rstd);
    __half* ctx  = (__half*)symaddr(h_ctx);  __half* cm0 = (__half*)symaddr(h_cm0);
    float*  hbuf = (float*)symaddr(g_h);     __half* xln = (__half*)symaddr(h_xln);
    __half* x1   = (__half*)symaddr(h_x1);
    __half* qwT  = (__half*)symaddr(h_qwT);  __half* kvwT= (__half*)symaddr(h_kvwT);
    __half* WqT  = (__half*)symaddr(h_WqT);  __half* WkT = (__half*)symaddr(h_WkT);
    __half* WvT  = (__half*)symaddr(h_WvT);  __half* WoT = (__half*)symaddr(h_WoT);
    __half* outwT= (__half*)symaddr(h_outwT);
    __half* fc1wT= (__half*)symaddr(h_fc1wT);__half* fc2wT=(__half*)symaddr(h_fc2wT);

    const long long Z = 0;
    dim3 tb(32, 8);

    // 1. fused LayerNorms
    ln_fused_kernel<<<BN_, 256>>>(emb[0], emb[1], emb[2], emb[3], lag, lab, lcg, lcb, cx, ec);

    // 2. weight transposes (fp32 -> half)
    transpose_t<float,__half><<<dim3(64,64,1), tb>>>(Wq, WqT, C_, C_, C_, 0, 0);
    transpose_t<float,__half><<<dim3(64,64,1), tb>>>(Wk, WkT, C_, C_, C_, 0, 0);
    transpose_t<float,__half><<<dim3(64,64,1), tb>>>(Wv, WvT, C_, C_, C_, 0, 0);
    transpose_t<float,__half><<<dim3(64,64,1), tb>>>(Wo, WoT, C_, C_, C_, 0, 0);
    transpose_t<float,__half><<<dim3(7,7,4),   tb>>>(q_w, qwT, N_, N_, LP_, (long long)N_*N_, (long long)N_*LP_);
    transpose_t<float,__half><<<dim3(25,25,1), tb>>>(k_w, kvwT, FN_, FN_, FN_, 0, 0);
    transpose_t<float,__half><<<dim3(25,25,1), tb>>>(v_w, kvwT + (long long)FN_*FN_, FN_, FN_, FN_, 0, 0);
    transpose_t<float,__half><<<dim3(16,16,4), tb>>>(outw, outwT, E_, E_, E_, (long long)E_*E_, (long long)E_*E_);
    transpose_t<float,__half><<<dim3(64,16,4), tb>>>(fc1w, fc1wT, E_, 2048, E_, (long long)E_*2048, (long long)2048*E_);
    transpose_t<float,__half><<<dim3(16,64,4), tb>>>(fc2w, fc2wT, 2048, E_, 2048, (long long)2048*E_, (long long)E_*2048);
    transpose_t<__half,__half><<<dim3(16,7,64), tb>>>(cx, cxT, N_, E_, LP_, (long long)NE_, (long long)E_*LP_);

    // 3. channel projections: [3136,2048,2048]
    {
        dim3 g(8, 25, 1);
        G2<<<g,256,SM2>>>(BN_, C_, C_, ec, C_, WqT, C_, qc, C_, nullptr, nullptr, 0, 1, 1.f,
                          1,1, Z,Z,Z, Z,Z,Z, Z,Z,Z, Z,Z);
        G2<<<g,256,SM2>>>(BN_, C_, C_, ec, C_, WkT, C_, kc, C_, nullptr, nullptr, 0, 1, 1.f,
                          1,1, Z,Z,Z, Z,Z,Z, Z,Z,Z, Z,Z);
        G2<<<g,256,SM2>>>(BN_, C_, C_, ec, C_, WvT, C_, vc, C_, nullptr, nullptr, 0, 1, 1.f,
                          1,1, Z,Z,Z, Z,Z,Z, Z,Z,Z, Z,Z);
    }
    transpose_t<__half,__half><<<dim3(64,7,16), tb>>>(vc, vcT, N_, C_, LP_, (long long)N_*C_, (long long)C_*LP_);

    // 4. channel scores per (h,b): [196,196,256] -> fp32 logits
    {
        dim3 g(2, 2, B_*H_);
        G1<<<g,256,SM1>>>(N_, N_, HDC_, qc, C_, kc, C_, sch, N_, nullptr, nullptr, 0, 0, 0.0625f,
                          H_, B_,
                          256LL, (long long)N_*C_, Z,
                          256LL, (long long)N_*C_, Z,
                          (long long)SCHZ_, (long long)H_*SCHZ_, Z,
                          Z, Z);
    }
    // 5. channel softmax -> half probs (padded rows)
    softmax_fix<1,false><<<B_*H_*N_, 256>>>(sch, schh, N_, LP_, 1, nullptr, 1.f);

    // 6. T = s @ v per (h,b): [196,256,196]
    {
        dim3 g(1, 2, B_*H_);
        G2<<<g,256,SM2>>>(N_, HDC_, N_, schh, LP_, vcT, LP_, tbuf, C_, nullptr, nullptr, 0, 1, 1.f,
                          H_, B_,
                          (long long)N_*LP_, (long long)H_*N_*LP_, Z,
                          (long long)256*LP_, (long long)C_*LP_, Z,
                          256LL, (long long)N_*C_, Z,
                          Z, Z);
    }
    // 7. T_hat = T @ Wo
    {
        dim3 g(8, 25, 1);
        G2<<<g,256,SM2>>>(BN_, C_, C_, tbuf, C_, WoT, C_, that, C_, nullptr, nullptr, 0, 1, 1.f,
                          1,1, Z,Z,Z, Z,Z,Z, Z,Z,Z, Z,Z);
    }
    // 8. fused KV_S reshape + transpose
    kvsT_kernel<<<dim3(16, 7, 64), tb>>>(that, kvsT);

    // 9. K/V token-mix merged: [784,512,784] per (which,b)
    {
        dim3 g(2, 7, 2*B_);
        G2<<<g,256,SM2>>>(FN_, E_, FN_, kvwT, FN_, kvsT, FN_, KV, E_, nullptr, nullptr, 0, 1, 1.f,
                          2, B_,
                          (long long)FN_*FN_, Z, Z,
                          Z, (long long)E_*FN_, Z,
                          (long long)B_*FNE_, (long long)FNE_, Z,
                          Z, Z);
    }
    transpose_t<__half,__half><<<dim3(16,25,16), tb>>>(KV + (long long)B_*FNE_, VT, FN_, E_, FN_,
                                                       (long long)FNE_, (long long)E_*FN_);

    // 10. Q token-mix per (b,g): [196,512,196]
    {
        dim3 g(2, 2, 4*B_);
        G2<<<g,256,SM2>>>(N_, E_, N_, qwT, LP_, cxT, LP_, Qb, E_, nullptr, nullptr, 0, 1, 1.f,
                          B_, 4,
                          Z, (long long)N_*LP_, Z,
                          (long long)E_*LP_, (long long)B_*E_*LP_, Z,
                          (long long)NE_, (long long)BNE_, Z,
                          Z, Z);
    }
    // 11. spatial logits per (h,b,g): [196,784,64] -> fp32
    {
        dim3 g(7, 2, 512);
        G1<<<g,256,SM1>>>(N_, FN_, HD_, Qb, E_, KV, E_, attn, FN_, nullptr, nullptr, 0, 0, 1.f,
                          H_, B_,
                          64LL, (long long)NE_,  (long long)BNE_,
                          64LL, (long long)FNE_, Z,
                          (long long)ATTZ_, (long long)H_*ATTZ_, (long long)B_*H_*ATTZ_,
                          Z, Z);
    }
    // 12-13. instance-norm rstd + softmax -> half probs
    inorm_stats_kernel<<<512, 512>>>(attn, rstdp);
    softmax_fix<4,true><<<512*N_, 256>>>(attn, attnh, FN_, FN_, N_, rstdp, 1.f);

    // 14. ctx = p @ Vh per (h,b,g): [196,64,784]
    {
        dim3 g(1, 2, 512);
        G3<<<g,256,SM3>>>(N_, HD_, FN_, attnh, FN_, VT, FN_, ctx, HD_, nullptr, nullptr, 0, 1, 1.f,
                          H_, B_,
                          (long long)ATTZ_, (long long)H_*ATTZ_, (long long)B_*H_*ATTZ_,
                          (long long)HD_*FN_, (long long)E_*FN_, Z,
                          (long long)N_*HD_, (long long)H_*N_*HD_, (long long)B_*H_*N_*HD_,
                          Z, Z);
    }
    // 15. branch-0 head permute
    merge0_kernel<<<(BN_*E_ + 255)/256, 256>>>(ctx, cm0);

    // 16. out projection + residual-1 (fp32 out)
    {
        dim3 g(2, 25, 1);
        for (int gg = 0; gg < 4; gg++) {
            const __half* Ag = (gg == 0) ? cm0 : (ctx + (long long)gg * BNE_);
            G2<<<g,256,SM2>>>(BN_, E_, E_, Ag, E_, outwT + (long long)gg*E_*E_, E_,
                              hbuf + (long long)gg*BNE_, E_,
                              nullptr, emb[gg], 0, 0, 1.f,
                              1,1, Z,Z,Z, Z,Z,Z, Z,Z,Z, Z,Z);
        }
    }
    // 17. FFN LayerNorm
    ln_rows_kernel<<<4*BN_, 256>>>(hbuf, lfg, lfb, xln, BN_);

    // 18. fc1 + bias + GELU per g: [3136,2048,512]
    {
        dim3 g(8, 25, 4);
        G2<<<g,256,SM2>>>(BN_, 4*E_, E_, xln, E_, fc1wT, E_, x1, 4*E_,
                          fc1b, nullptr, 1, 1, 1.f,
                          4, 1,
                          (long long)BNE_, Z, Z,
                          (long long)2048*E_, Z, Z,
                          (long long)BN_*2048, Z, Z,
                          (long long)2048, Z);
    }
    // 19. fc2 + bias + residual-2 -> out (fp32)
    {
        dim3 g(2, 25, 4);
        G2<<<g,256,SM2>>>(BN_, E_, 4*E_, x1, 4*E_, fc2wT, 4*E_, out, E_,
                          fc2b, hbuf, 0, 0, 1.f,
                          4, 1,
                          (long long)BN_*2048, Z, Z,
                          (long long)E_*2048, Z, Z,
                          (long long)BNE_, Z, Z,
                          (long long)E_, (long long)BNE_);
    }
}